// round 2
// baseline (speedup 1.0000x reference)
#include <cuda_runtime.h>
#include <math.h>

// Problem constants
#define Bz   4
#define Nn   2048
#define Cc   1024
#define Hh   8
#define Dd   128
#define Mm   (Bz * Nn)          // 8192 tokens
#define C3   (3 * Cc)           // 3072
#define EPS  1e-5f
#define ATT_SCALE 0.08838834764831845f  // 128^-0.5

// ---------------- scratch (device globals; no allocation) ----------------
__device__ float g_h   [Mm * Cc];   // LN output (reused for LN1 and LN2)
__device__ float g_qkv [Mm * C3];   // qkv projection
__device__ float g_attn[Mm * Cc];   // attention output (B,N,C)
__device__ float g_x1  [Mm * Cc];   // x after attention residual
__device__ float g_h1  [Mm * Cc];   // MLP hidden
__device__ float g_wqkvT [Cc * C3]; // transposed weights [K, Nout]
__device__ float g_wprojT[Cc * Cc];
__device__ float g_w1T   [Cc * Cc];
__device__ float g_w2T   [Cc * Cc];

// ---------------- transpose: src[rows,cols] -> dst[cols,rows] ----------------
__global__ void transpose_k(const float* __restrict__ src, float* __restrict__ dst,
                            int rows, int cols)
{
    __shared__ float tile[32][33];
    int c = blockIdx.x * 32 + threadIdx.x;
    int rbase = blockIdx.y * 32;
    #pragma unroll
    for (int i = threadIdx.y; i < 32; i += 8)
        tile[i][threadIdx.x] = src[(size_t)(rbase + i) * cols + c];
    __syncthreads();
    int c2 = blockIdx.y * 32 + threadIdx.x;   // out col = orig row
    int r2base = blockIdx.x * 32;             // out row = orig col
    #pragma unroll
    for (int i = threadIdx.y; i < 32; i += 8)
        dst[(size_t)(r2base + i) * rows + c2] = tile[threadIdx.x][i];
}

// ---------------- LayerNorm: one block (256 thr) per row of 1024 ----------------
__global__ void layernorm_k(const float* __restrict__ in, const float* __restrict__ g,
                            const float* __restrict__ b, float* __restrict__ out)
{
    int row = blockIdx.x;
    int t = threadIdx.x;
    const float4* inr = (const float4*)(in + (size_t)row * Cc);
    float4 v = inr[t];
    float s  = v.x + v.y + v.z + v.w;
    float ss = v.x*v.x + v.y*v.y + v.z*v.z + v.w*v.w;
    #pragma unroll
    for (int o = 16; o; o >>= 1) {
        s  += __shfl_xor_sync(0xffffffffu, s,  o);
        ss += __shfl_xor_sync(0xffffffffu, ss, o);
    }
    __shared__ float sm1[8], sm2[8];
    if ((t & 31) == 0) { sm1[t >> 5] = s; sm2[t >> 5] = ss; }
    __syncthreads();
    if (t < 32) {
        s  = (t < 8) ? sm1[t] : 0.f;
        ss = (t < 8) ? sm2[t] : 0.f;
        #pragma unroll
        for (int o = 4; o; o >>= 1) {
            s  += __shfl_xor_sync(0xffffffffu, s,  o);
            ss += __shfl_xor_sync(0xffffffffu, ss, o);
        }
        if (t == 0) { sm1[0] = s; sm2[0] = ss; }
    }
    __syncthreads();
    float mu  = sm1[0] * (1.f / Cc);
    float var = sm2[0] * (1.f / Cc) - mu * mu;
    float inv = rsqrtf(var + EPS);
    float4 gv = ((const float4*)g)[t];
    float4 bv = ((const float4*)b)[t];
    float4 o4;
    o4.x = (v.x - mu) * inv * gv.x + bv.x;
    o4.y = (v.y - mu) * inv * gv.y + bv.y;
    o4.z = (v.z - mu) * inv * gv.z + bv.z;
    o4.w = (v.w - mu) * inv * gv.w + bv.w;
    ((float4*)(out + (size_t)row * Cc))[t] = o4;
}

// ---------------- SGEMM 128x128x8, 8x8 per thread, fused epilogues ----------------
// C[M,N] = A[M,K] @ Bt[K,N] ; EPI: 0 none | 1 +bias+res | 2 +bias,ELU | 3 +bias,ELU,BN,+res
template <int EPI>
__global__ __launch_bounds__(256)
void sgemm_k(const float* __restrict__ A, const float* __restrict__ Bt,
             float* __restrict__ Cmat,
             const float* __restrict__ bias, const float* __restrict__ res,
             const float* __restrict__ bng, const float* __restrict__ bnb,
             const float* __restrict__ bnm, const float* __restrict__ bnv,
             int Mdim, int Ndim, int Kdim)
{
    __shared__ float As[8][128];
    __shared__ float Bs[8][132];
    const int tid   = threadIdx.x;
    const int m_blk = blockIdx.y * 128;
    const int n_blk = blockIdx.x * 128;
    const int tx = tid & 15, ty = tid >> 4;
    const int mf = ty * 8, nf = tx * 8;

    float acc[8][8];
    #pragma unroll
    for (int i = 0; i < 8; i++)
        #pragma unroll
        for (int j = 0; j < 8; j++) acc[i][j] = 0.f;

    const int ar = tid >> 1;          // A tile row 0..127
    const int ac = (tid & 1) * 4;     // A tile k-offset 0 or 4
    const int bk = tid >> 5;          // B tile k 0..7
    const int bn = (tid & 31) * 4;    // B tile n-offset
    const float* Aptr = A + (size_t)(m_blk + ar) * Kdim + ac;
    const float* Bptr = Bt + (size_t)bk * Ndim + n_blk + bn;

    for (int k0 = 0; k0 < Kdim; k0 += 8) {
        float4 av = *(const float4*)(Aptr + k0);
        float4 bv = *(const float4*)(Bptr + (size_t)k0 * Ndim);
        As[ac + 0][ar] = av.x; As[ac + 1][ar] = av.y;
        As[ac + 2][ar] = av.z; As[ac + 3][ar] = av.w;
        *(float4*)&Bs[bk][bn] = bv;
        __syncthreads();
        #pragma unroll
        for (int kk = 0; kk < 8; kk++) {
            float ra[8], rb[8];
            *(float4*)(ra)     = *(const float4*)&As[kk][mf];
            *(float4*)(ra + 4) = *(const float4*)&As[kk][mf + 4];
            *(float4*)(rb)     = *(const float4*)&Bs[kk][nf];
            *(float4*)(rb + 4) = *(const float4*)&Bs[kk][nf + 4];
            #pragma unroll
            for (int i = 0; i < 8; i++)
                #pragma unroll
                for (int j = 0; j < 8; j++)
                    acc[i][j] = fmaf(ra[i], rb[j], acc[i][j]);
        }
        __syncthreads();
    }

    #pragma unroll
    for (int i = 0; i < 8; i++) {
        int row = m_blk + mf + i;
        float* crow = Cmat + (size_t)row * Ndim + n_blk + nf;
        const float* rrow = (EPI == 1 || EPI == 3)
                          ? res + (size_t)row * Ndim + n_blk + nf : nullptr;
        float vout[8];
        #pragma unroll
        for (int j = 0; j < 8; j++) {
            float v = acc[i][j];
            int col = n_blk + nf + j;
            if (EPI == 1) {
                v = v + bias[col] + rrow[j];
            } else if (EPI == 2) {
                v += bias[col];
                v = (v > 0.f) ? v : expm1f(v);
            } else if (EPI == 3) {
                v += bias[col];
                v = (v > 0.f) ? v : expm1f(v);
                float inv = rsqrtf(bnv[col] + EPS);
                v = (v - bnm[col]) * inv * bng[col] + bnb[col];
                v += rrow[j];
            }
            vout[j] = v;
        }
        *(float4*)(crow)     = *(float4*)(vout);
        *(float4*)(crow + 4) = *(float4*)(vout + 4);
    }
}

// ---------------- Flash attention (fp32), BQ=64, BK=64, D=128 ----------------
// grid: (N/64, B*H), 256 threads, dynamic smem.
#define QSTRIDE 68   // 64 + 4 pad (16B-aligned rows: 68*4=272)
#define VSTRIDE 132  // 128 + 4 pad (528B rows, 16B-aligned)
#define NEG_BIG (-1e30f)

__global__ __launch_bounds__(256, 2)
void flash_k(const float* __restrict__ qkv, float* __restrict__ attn_out)
{
    extern __shared__ float sm[];
    float* QsT  = sm;                       // [128][68] : QsT[d][i]
    float* KVs  = sm + 128 * QSTRIDE;       // K phase: [128][68] KsT[d][j]; V phase: [64][132] Vs[j][d]
    float* PsT  = sm + 2 * 128 * QSTRIDE;   // [64][68] : PsT[j][i]
    float* m_s  = PsT + 64 * QSTRIDE;
    float* l_s  = m_s + 64;
    float* al_s = l_s + 64;

    const int tid = threadIdx.x;
    const int bh = blockIdx.y;
    const int b = bh >> 3, h = bh & 7;
    const int q0 = blockIdx.x * 64;
    const size_t base = (size_t)b * Nn * C3;

    // load Q tile transposed
    #pragma unroll
    for (int it = 0; it < 8; it++) {
        int idx = tid + it * 256;
        int i = idx >> 5; int d4 = (idx & 31) << 2;
        float4 v = *(const float4*)(qkv + base + (size_t)(q0 + i) * C3 + h * Dd + d4);
        QsT[(d4 + 0) * QSTRIDE + i] = v.x;
        QsT[(d4 + 1) * QSTRIDE + i] = v.y;
        QsT[(d4 + 2) * QSTRIDE + i] = v.z;
        QsT[(d4 + 3) * QSTRIDE + i] = v.w;
    }
    if (tid < 64) { m_s[tid] = NEG_BIG; l_s[tid] = 0.f; }

    float accO[4][8];
    #pragma unroll
    for (int i = 0; i < 4; i++)
        #pragma unroll
        for (int d = 0; d < 8; d++) accO[i][d] = 0.f;

    const int tx = tid & 15, ty = tid >> 4;
    const int i0 = tx * 4;   // query rows for S / PV / output
    const int j0 = ty * 4;   // key cols for S
    const int d0 = ty * 8;   // dims for PV / output

    for (int kt = 0; kt < Nn / 64; kt++) {
        __syncthreads();   // protect smem reuse from previous iter
        // load K tile transposed
        #pragma unroll
        for (int it = 0; it < 8; it++) {
            int idx = tid + it * 256;
            int j = idx >> 5; int d4 = (idx & 31) << 2;
            float4 v = *(const float4*)(qkv + base + (size_t)(kt * 64 + j) * C3 + Cc + h * Dd + d4);
            KVs[(d4 + 0) * QSTRIDE + j] = v.x;
            KVs[(d4 + 1) * QSTRIDE + j] = v.y;
            KVs[(d4 + 2) * QSTRIDE + j] = v.z;
            KVs[(d4 + 3) * QSTRIDE + j] = v.w;
        }
        __syncthreads();
        // S = scale * Q K^T  (each thread 4x4)
        float sacc[4][4];
        #pragma unroll
        for (int a = 0; a < 4; a++)
            #pragma unroll
            for (int c = 0; c < 4; c++) sacc[a][c] = 0.f;
        #pragma unroll 4
        for (int d = 0; d < 128; d++) {
            float4 qv = *(const float4*)&QsT[d * QSTRIDE + i0];
            float4 kv = *(const float4*)&KVs[d * QSTRIDE + j0];
            float q[4] = {qv.x, qv.y, qv.z, qv.w};
            float k[4] = {kv.x, kv.y, kv.z, kv.w};
            #pragma unroll
            for (int a = 0; a < 4; a++)
                #pragma unroll
                for (int c = 0; c < 4; c++)
                    sacc[a][c] = fmaf(q[a], k[c], sacc[a][c]);
        }
        #pragma unroll
        for (int c = 0; c < 4; c++)
            #pragma unroll
            for (int a = 0; a < 4; a++)
                PsT[(j0 + c) * QSTRIDE + i0 + a] = sacc[a][c] * ATT_SCALE;
        __syncthreads();
        // load V tile (row-major [j][d]) into the K buffer
        #pragma unroll
        for (int it = 0; it < 8; it++) {
            int idx = tid + it * 256;
            int j = idx >> 5; int d4 = (idx & 31) << 2;
            float4 v = *(const float4*)(qkv + base + (size_t)(kt * 64 + j) * C3 + 2 * Cc + h * Dd + d4);
            *(float4*)&KVs[j * VSTRIDE + d4] = v;
        }
        // online softmax stats: warp w owns rows w*8 .. w*8+7
        {
            int w = tid >> 5, lane = tid & 31;
            for (int r = 0; r < 8; r++) {
                int i = w * 8 + r;
                float s1 = PsT[lane * QSTRIDE + i];
                float s2 = PsT[(lane + 32) * QSTRIDE + i];
                float mx = fmaxf(s1, s2);
                #pragma unroll
                for (int o = 16; o; o >>= 1)
                    mx = fmaxf(mx, __shfl_xor_sync(0xffffffffu, mx, o));
                float m_old = m_s[i];
                float m_new = fmaxf(m_old, mx);
                float p1 = __expf(s1 - m_new);
                float p2 = __expf(s2 - m_new);
                PsT[lane * QSTRIDE + i] = p1;
                PsT[(lane + 32) * QSTRIDE + i] = p2;
                float ps = p1 + p2;
                #pragma unroll
                for (int o = 16; o; o >>= 1)
                    ps += __shfl_xor_sync(0xffffffffu, ps, o);
                if (lane == 0) {
                    float alpha = __expf(m_old - m_new);
                    l_s[i] = l_s[i] * alpha + ps;
                    m_s[i] = m_new;
                    al_s[i] = alpha;
                }
            }
        }
        __syncthreads();
        // rescale + accumulate O += P @ V
        #pragma unroll
        for (int a = 0; a < 4; a++) {
            float alp = al_s[i0 + a];
            #pragma unroll
            for (int d = 0; d < 8; d++) accO[a][d] *= alp;
        }
        #pragma unroll 8
        for (int j = 0; j < 64; j++) {
            float4 pv = *(const float4*)&PsT[j * QSTRIDE + i0];
            float4 v0 = *(const float4*)&KVs[j * VSTRIDE + d0];
            float4 v1 = *(const float4*)&KVs[j * VSTRIDE + d0 + 4];
            float p[4] = {pv.x, pv.y, pv.z, pv.w};
            float vv[8] = {v0.x, v0.y, v0.z, v0.w, v1.x, v1.y, v1.z, v1.w};
            #pragma unroll
            for (int a = 0; a < 4; a++)
                #pragma unroll
                for (int d = 0; d < 8; d++)
                    accO[a][d] = fmaf(p[a], vv[d], accO[a][d]);
        }
    }
    // write O / l
    #pragma unroll
    for (int a = 0; a < 4; a++) {
        int n = q0 + i0 + a;
        float invl = 1.f / l_s[i0 + a];
        float o8[8];
        #pragma unroll
        for (int d = 0; d < 8; d++) o8[d] = accO[a][d] * invl;
        float* dst = attn_out + ((size_t)b * Nn + n) * Cc + h * Dd + d0;
        *(float4*)(dst)     = *(float4*)(o8);
        *(float4*)(dst + 4) = *(float4*)(o8 + 4);
    }
}

// ---------------- host launcher ----------------
extern "C" void kernel_launch(void* const* d_in, const int* in_sizes, int n_in,
                              void* d_out, int out_size)
{
    const float* x       = (const float*)d_in[0];
    const float* ln1_g   = (const float*)d_in[1];
    const float* ln1_b   = (const float*)d_in[2];
    const float* w_qkv   = (const float*)d_in[3];
    const float* w_proj  = (const float*)d_in[4];
    const float* b_proj  = (const float*)d_in[5];
    const float* ln2_g   = (const float*)d_in[6];
    const float* ln2_b   = (const float*)d_in[7];
    const float* w1      = (const float*)d_in[8];
    const float* b1      = (const float*)d_in[9];
    const float* w2      = (const float*)d_in[10];
    const float* b2      = (const float*)d_in[11];
    const float* bn_g    = (const float*)d_in[12];
    const float* bn_b    = (const float*)d_in[13];
    const float* bn_mean = (const float*)d_in[14];
    const float* bn_var  = (const float*)d_in[15];
    float* out = (float*)d_out;

    float *p_h, *p_qkv, *p_attn, *p_x1, *p_h1;
    float *p_wqkvT, *p_wprojT, *p_w1T, *p_w2T;
    cudaGetSymbolAddress((void**)&p_h,      g_h);
    cudaGetSymbolAddress((void**)&p_qkv,    g_qkv);
    cudaGetSymbolAddress((void**)&p_attn,   g_attn);
    cudaGetSymbolAddress((void**)&p_x1,     g_x1);
    cudaGetSymbolAddress((void**)&p_h1,     g_h1);
    cudaGetSymbolAddress((void**)&p_wqkvT,  g_wqkvT);
    cudaGetSymbolAddress((void**)&p_wprojT, g_wprojT);
    cudaGetSymbolAddress((void**)&p_w1T,    g_w1T);
    cudaGetSymbolAddress((void**)&p_w2T,    g_w2T);

    dim3 tb(32, 8);
    transpose_k<<<dim3(Cc / 32, C3 / 32), tb>>>(w_qkv,  p_wqkvT,  C3, Cc);
    transpose_k<<<dim3(Cc / 32, Cc / 32), tb>>>(w_proj, p_wprojT, Cc, Cc);
    transpose_k<<<dim3(Cc / 32, Cc / 32), tb>>>(w1,     p_w1T,    Cc, Cc);
    transpose_k<<<dim3(Cc / 32, Cc / 32), tb>>>(w2,     p_w2T,    Cc, Cc);

    // LN1
    layernorm_k<<<Mm, 256>>>(x, ln1_g, ln1_b, p_h);

    // QKV GEMM: [8192,1024] @ [1024,3072]
    sgemm_k<0><<<dim3(C3 / 128, Mm / 128), 256>>>(
        p_h, p_wqkvT, p_qkv, nullptr, nullptr, nullptr, nullptr, nullptr, nullptr,
        Mm, C3, Cc);

    // Flash attention
    int smem_bytes = (2 * 128 * QSTRIDE + 64 * QSTRIDE + 3 * 64) * (int)sizeof(float);
    cudaFuncSetAttribute(flash_k, cudaFuncAttributeMaxDynamicSharedMemorySize, smem_bytes);
    flash_k<<<dim3(Nn / 64, Bz * Hh), 256, smem_bytes>>>(p_qkv, p_attn);

    // proj GEMM + bias + residual -> x1
    sgemm_k<1><<<dim3(Cc / 128, Mm / 128), 256>>>(
        p_attn, p_wprojT, p_x1, b_proj, x, nullptr, nullptr, nullptr, nullptr,
        Mm, Cc, Cc);

    // LN2
    layernorm_k<<<Mm, 256>>>(p_x1, ln2_g, ln2_b, p_h);

    // MLP1: ELU(h @ w1^T + b1)
    sgemm_k<2><<<dim3(Cc / 128, Mm / 128), 256>>>(
        p_h, p_w1T, p_h1, b1, nullptr, nullptr, nullptr, nullptr, nullptr,
        Mm, Cc, Cc);

    // MLP2: out = x1 + BN(ELU(h1 @ w2^T + b2))
    sgemm_k<3><<<dim3(Cc / 128, Mm / 128), 256>>>(
        p_h1, p_w2T, out, b2, p_x1, bn_g, bn_b, bn_mean, bn_var,
        Mm, Cc, Cc);
}

// round 8
// speedup vs baseline: 1.5230x; 1.5230x over previous
#include <cuda_runtime.h>
#include <cuda_bf16.h>
#include <math.h>
#include <stdint.h>

// Problem constants
#define Bz   4
#define Nn   2048
#define Cc   1024
#define Hh   8
#define Dd   128
#define Mm   (Bz * Nn)          // 8192 tokens
#define C3   (3 * Cc)           // 3072
#define EPS  1e-5f
#define ATT_SCALE 0.08838834764831845f  // 128^-0.5

// ================= PTX helpers (plain sm_103-safe: sm_80-era features) ======
__device__ __forceinline__ uint32_t smem_u32(const void* p) {
    uint32_t a;
    asm("{ .reg .u64 t; cvta.to.shared.u64 t, %1; cvt.u32.u64 %0, t; }" : "=r"(a) : "l"(p));
    return a;
}
#define CP_ASYNC(dst, src) \
    asm volatile("cp.async.cg.shared.global [%0], [%1], 16;" :: "r"(dst), "l"(src))
#define CP_COMMIT() asm volatile("cp.async.commit_group;" ::: "memory")
#define CP_WAIT1()  asm volatile("cp.async.wait_group 1;" ::: "memory")
#define CP_WAIT0()  asm volatile("cp.async.wait_group 0;" ::: "memory")

__device__ __forceinline__ void ldsm_x4(uint32_t& r0, uint32_t& r1, uint32_t& r2, uint32_t& r3,
                                        uint32_t addr) {
    asm volatile("ldmatrix.sync.aligned.m8n8.x4.shared.b16 {%0,%1,%2,%3}, [%4];"
                 : "=r"(r0), "=r"(r1), "=r"(r2), "=r"(r3) : "r"(addr));
}
__device__ __forceinline__ void mma_bf16(float* d, const uint32_t* a, const uint32_t* b) {
    asm volatile(
        "mma.sync.aligned.m16n8k16.row.col.f32.bf16.bf16.f32 "
        "{%0,%1,%2,%3}, {%4,%5,%6,%7}, {%8,%9}, {%0,%1,%2,%3};"
        : "+f"(d[0]), "+f"(d[1]), "+f"(d[2]), "+f"(d[3])
        : "r"(a[0]), "r"(a[1]), "r"(a[2]), "r"(a[3]), "r"(b[0]), "r"(b[1]));
}

// hi/lo bf16 split of two floats packed into uint32 (elem0 in low half)
__device__ __forceinline__ void split2(float a, float b, uint32_t& hp, uint32_t& lp) {
    __nv_bfloat16 ha = __float2bfloat16(a), hb = __float2bfloat16(b);
    float ra = a - __bfloat162float(ha), rb = b - __bfloat162float(hb);
    __nv_bfloat16 la = __float2bfloat16(ra), lb = __float2bfloat16(rb);
    hp = (uint32_t)__bfloat16_as_ushort(ha) | ((uint32_t)__bfloat16_as_ushort(hb) << 16);
    lp = (uint32_t)__bfloat16_as_ushort(la) | ((uint32_t)__bfloat16_as_ushort(lb) << 16);
}

// ================= scratch (device globals) =================
__device__ float g_qkv[Mm * C3];
__device__ float g_x1 [Mm * Cc];
__device__ __nv_bfloat16 g_h_hi   [Mm * Cc], g_h_lo   [Mm * Cc];
__device__ __nv_bfloat16 g_attn_hi[Mm * Cc], g_attn_lo[Mm * Cc];
__device__ __nv_bfloat16 g_h1_hi  [Mm * Cc], g_h1_lo  [Mm * Cc];
__device__ __nv_bfloat16 g_wqkv_hi [C3 * Cc], g_wqkv_lo [C3 * Cc];
__device__ __nv_bfloat16 g_wproj_hi[Cc * Cc], g_wproj_lo[Cc * Cc];
__device__ __nv_bfloat16 g_w1_hi   [Cc * Cc], g_w1_lo   [Cc * Cc];
__device__ __nv_bfloat16 g_w2_hi   [Cc * Cc], g_w2_lo   [Cc * Cc];

// ================= fp32 -> bf16 hi/lo converter =================
__global__ void cvt_split_k(const float* __restrict__ w,
                            __nv_bfloat16* __restrict__ hi, __nv_bfloat16* __restrict__ lo)
{
    int i = blockIdx.x * 256 + threadIdx.x;
    float4 v = ((const float4*)w)[i];
    uint32_t h0, l0, h1, l1;
    split2(v.x, v.y, h0, l0);
    split2(v.z, v.w, h1, l1);
    ((uint2*)hi)[i] = make_uint2(h0, h1);
    ((uint2*)lo)[i] = make_uint2(l0, l1);
}

// ================= LayerNorm -> bf16 hi/lo =================
__global__ void layernorm_bf_k(const float* __restrict__ in, const float* __restrict__ g,
                               const float* __restrict__ b,
                               __nv_bfloat16* __restrict__ hi, __nv_bfloat16* __restrict__ lo)
{
    int row = blockIdx.x;
    int t = threadIdx.x;
    const float4* inr = (const float4*)(in + (size_t)row * Cc);
    float4 v = inr[t];
    float s  = v.x + v.y + v.z + v.w;
    float ss = v.x*v.x + v.y*v.y + v.z*v.z + v.w*v.w;
    #pragma unroll
    for (int o = 16; o; o >>= 1) {
        s  += __shfl_xor_sync(0xffffffffu, s,  o);
        ss += __shfl_xor_sync(0xffffffffu, ss, o);
    }
    __shared__ float sm1[8], sm2[8];
    if ((t & 31) == 0) { sm1[t >> 5] = s; sm2[t >> 5] = ss; }
    __syncthreads();
    if (t < 32) {
        s  = (t < 8) ? sm1[t] : 0.f;
        ss = (t < 8) ? sm2[t] : 0.f;
        #pragma unroll
        for (int o = 4; o; o >>= 1) {
            s  += __shfl_xor_sync(0xffffffffu, s,  o);
            ss += __shfl_xor_sync(0xffffffffu, ss, o);
        }
        if (t == 0) { sm1[0] = s; sm2[0] = ss; }
    }
    __syncthreads();
    float mu  = sm1[0] * (1.f / Cc);
    float var = sm2[0] * (1.f / Cc) - mu * mu;
    float inv = rsqrtf(var + EPS);
    float4 gv = ((const float4*)g)[t];
    float4 bv = ((const float4*)b)[t];
    float o0 = (v.x - mu) * inv * gv.x + bv.x;
    float o1 = (v.y - mu) * inv * gv.y + bv.y;
    float o2 = (v.z - mu) * inv * gv.z + bv.z;
    float o3 = (v.w - mu) * inv * gv.w + bv.w;
    uint32_t h0, l0, h1, l1;
    split2(o0, o1, h0, l0);
    split2(o2, o3, h1, l1);
    ((uint2*)(hi + (size_t)row * Cc))[t] = make_uint2(h0, h1);
    ((uint2*)(lo + (size_t)row * Cc))[t] = make_uint2(l0, l1);
}

// ================= mma.sync split-bf16 GEMM =================
// C[M,N] = A[M,K] @ B[N,K]^T via AhiBhi + AhiBlo + AloBhi, fp32 accum.
// Tile 128x128xK_CHUNK=64; 8 warps: warp_m=wid&3 (32 rows), warp_n=wid>>2 (64 cols).
// EPI: 0 fp32 | 1 +bias+res fp32 | 2 +bias,ELU -> bf16 hi/lo | 3 +bias,ELU,BN,+res fp32
#define BK      64
#define SSTRIDE 72                     // bf16 elems per smem row (64 + 8 pad)
#define TILE_B  (128 * SSTRIDE * 2)    // bytes per tile buffer = 18432
#define STAGE_B (4 * TILE_B)           // Ahi, Alo, Bhi, Blo  = 73728
#define HG_SMEM (2 * STAGE_B)          // 147456

template <int EPI>
__global__ __launch_bounds__(256, 1)
void hgemm_k(const __nv_bfloat16* __restrict__ Ahi, const __nv_bfloat16* __restrict__ Alo,
             const __nv_bfloat16* __restrict__ Bhi, const __nv_bfloat16* __restrict__ Blo,
             float* __restrict__ Cf, __nv_bfloat16* __restrict__ Chi, __nv_bfloat16* __restrict__ Clo,
             const float* __restrict__ bias, const float* __restrict__ res,
             const float* __restrict__ bng, const float* __restrict__ bnb,
             const float* __restrict__ bnm, const float* __restrict__ bnv,
             int Ndim, int Kdim)
{
    extern __shared__ char dsm[];
    const int tid = threadIdx.x;
    const int wid = tid >> 5, lid = tid & 31;
    const int m_blk = blockIdx.y * 128, n_blk = blockIdx.x * 128;
    const int wm = wid & 3, wn = wid >> 2;

    const uint32_t sbase = smem_u32(dsm);

    float acc[2][8][4];
    #pragma unroll
    for (int i = 0; i < 2; i++)
        #pragma unroll
        for (int j = 0; j < 8; j++)
            #pragma unroll
            for (int q = 0; q < 4; q++) acc[i][j][q] = 0.f;

    // ldmatrix lane address components
    const int a_row = 32 * wm + (lid & 15);
    const int a_col = (lid >> 4) * 8;
    const int b_row = 64 * wn + ((lid & 16) >> 1) + (lid & 7);
    const int b_col = (lid & 8);

    // ---- async stage loader ----
    auto load_stage = [&](int c) {
        const int kk = c * BK;
        const uint32_t sb = sbase + (c & 1) * STAGE_B;
        #pragma unroll
        for (int it = 0; it < 4; ++it) {
            int id = tid + it * 256;
            int row = id >> 3, seg = id & 7;
            uint32_t so = (uint32_t)(row * SSTRIDE + seg * 8) * 2;
            size_t ga = (size_t)(m_blk + row) * Kdim + kk + seg * 8;
            size_t gb = (size_t)(n_blk + row) * Kdim + kk + seg * 8;
            CP_ASYNC(sb + so,              Ahi + ga);
            CP_ASYNC(sb + TILE_B + so,     Alo + ga);
            CP_ASYNC(sb + 2 * TILE_B + so, Bhi + gb);
            CP_ASYNC(sb + 3 * TILE_B + so, Blo + gb);
        }
        CP_COMMIT();
    };

    const int nchunk = Kdim / BK;
    load_stage(0);
    for (int c = 0; c < nchunk; ++c) {
        if (c + 1 < nchunk) { load_stage(c + 1); CP_WAIT1(); }
        else                { CP_WAIT0(); }
        __syncthreads();
        const uint32_t sb = sbase + (c & 1) * STAGE_B;
        #pragma unroll
        for (int k16 = 0; k16 < BK / 16; ++k16) {
            uint32_t ah[2][4], al[2][4], bh[8][2], bl[8][2];
            #pragma unroll
            for (int i = 0; i < 2; ++i) {
                uint32_t ao = sb + (uint32_t)((a_row + 16 * i) * SSTRIDE + a_col + 16 * k16) * 2;
                ldsm_x4(ah[i][0], ah[i][1], ah[i][2], ah[i][3], ao);
                ldsm_x4(al[i][0], al[i][1], al[i][2], al[i][3], ao + TILE_B);
            }
            #pragma unroll
            for (int jj = 0; jj < 4; ++jj) {
                uint32_t bo = sb + 2 * TILE_B
                            + (uint32_t)((b_row + 16 * jj) * SSTRIDE + b_col + 16 * k16) * 2;
                ldsm_x4(bh[2*jj][0], bh[2*jj][1], bh[2*jj+1][0], bh[2*jj+1][1], bo);
                ldsm_x4(bl[2*jj][0], bl[2*jj][1], bl[2*jj+1][0], bl[2*jj+1][1], bo + TILE_B);
            }
            #pragma unroll
            for (int i = 0; i < 2; ++i)
                #pragma unroll
                for (int j = 0; j < 8; ++j) {
                    mma_bf16(acc[i][j], ah[i], bh[j]);
                    mma_bf16(acc[i][j], ah[i], bl[j]);
                    mma_bf16(acc[i][j], al[i], bh[j]);
                }
        }
        __syncthreads();
    }

    // ---------------- epilogue ----------------
    #pragma unroll
    for (int i = 0; i < 2; ++i) {
        #pragma unroll
        for (int half = 0; half < 2; ++half) {
            const int r = m_blk + 32 * wm + 16 * i + (lid >> 2) + 8 * half;
            #pragma unroll
            for (int j = 0; j < 8; ++j) {
                const int c = n_blk + 64 * wn + 8 * j + 2 * (lid & 3);
                float v0 = acc[i][j][2 * half + 0];
                float v1 = acc[i][j][2 * half + 1];
                if (EPI == 1) {
                    const float2 rv = *(const float2*)(res + (size_t)r * Ndim + c);
                    v0 += __ldg(bias + c)     + rv.x;
                    v1 += __ldg(bias + c + 1) + rv.y;
                } else if (EPI == 2) {
                    v0 += __ldg(bias + c);
                    v1 += __ldg(bias + c + 1);
                    v0 = (v0 > 0.f) ? v0 : expm1f(v0);
                    v1 = (v1 > 0.f) ? v1 : expm1f(v1);
                } else if (EPI == 3) {
                    const float2 rv = *(const float2*)(res + (size_t)r * Ndim + c);
                    v0 += __ldg(bias + c);
                    v1 += __ldg(bias + c + 1);
                    v0 = (v0 > 0.f) ? v0 : expm1f(v0);
                    v1 = (v1 > 0.f) ? v1 : expm1f(v1);
                    v0 = (v0 - __ldg(bnm + c))     * rsqrtf(__ldg(bnv + c) + EPS)     * __ldg(bng + c)     + __ldg(bnb + c)     + rv.x;
                    v1 = (v1 - __ldg(bnm + c + 1)) * rsqrtf(__ldg(bnv + c + 1) + EPS) * __ldg(bng + c + 1) + __ldg(bnb + c + 1) + rv.y;
                }
                if (EPI == 2) {
                    uint32_t hp, lp;
                    split2(v0, v1, hp, lp);
                    *(uint32_t*)(Chi + (size_t)r * Ndim + c) = hp;
                    *(uint32_t*)(Clo + (size_t)r * Ndim + c) = lp;
                } else {
                    *(float2*)(Cf + (size_t)r * Ndim + c) = make_float2(v0, v1);
                }
            }
        }
    }
}

// ================= Flash attention (fp32 SIMT), writes bf16 hi/lo =================
#define QSTRIDE 68
#define VSTRIDE 132
#define NEG_BIG (-1e30f)

__global__ __launch_bounds__(256, 2)
void flash_k(const float* __restrict__ qkv,
             __nv_bfloat16* __restrict__ out_hi, __nv_bfloat16* __restrict__ out_lo)
{
    extern __shared__ float sm[];
    float* QsT  = sm;
    float* KVs  = sm + 128 * QSTRIDE;
    float* PsT  = sm + 2 * 128 * QSTRIDE;
    float* m_s  = PsT + 64 * QSTRIDE;
    float* l_s  = m_s + 64;
    float* al_s = l_s + 64;

    const int tid = threadIdx.x;
    const int bh = blockIdx.y;
    const int b = bh >> 3, h = bh & 7;
    const int q0 = blockIdx.x * 64;
    const size_t base = (size_t)b * Nn * C3;

    #pragma unroll
    for (int it = 0; it < 8; it++) {
        int idx = tid + it * 256;
        int i = idx >> 5; int d4 = (idx & 31) << 2;
        float4 v = *(const float4*)(qkv + base + (size_t)(q0 + i) * C3 + h * Dd + d4);
        QsT[(d4 + 0) * QSTRIDE + i] = v.x;
        QsT[(d4 + 1) * QSTRIDE + i] = v.y;
        QsT[(d4 + 2) * QSTRIDE + i] = v.z;
        QsT[(d4 + 3) * QSTRIDE + i] = v.w;
    }
    if (tid < 64) { m_s[tid] = NEG_BIG; l_s[tid] = 0.f; }

    float accO[4][8];
    #pragma unroll
    for (int i = 0; i < 4; i++)
        #pragma unroll
        for (int d = 0; d < 8; d++) accO[i][d] = 0.f;

    const int tx = tid & 15, ty = tid >> 4;
    const int i0 = tx * 4;
    const int j0 = ty * 4;
    const int d0 = ty * 8;

    for (int kt = 0; kt < Nn / 64; kt++) {
        __syncthreads();
        #pragma unroll
        for (int it = 0; it < 8; it++) {
            int idx = tid + it * 256;
            int j = idx >> 5; int d4 = (idx & 31) << 2;
            float4 v = *(const float4*)(qkv + base + (size_t)(kt * 64 + j) * C3 + Cc + h * Dd + d4);
            KVs[(d4 + 0) * QSTRIDE + j] = v.x;
            KVs[(d4 + 1) * QSTRIDE + j] = v.y;
            KVs[(d4 + 2) * QSTRIDE + j] = v.z;
            KVs[(d4 + 3) * QSTRIDE + j] = v.w;
        }
        __syncthreads();
        float sacc[4][4];
        #pragma unroll
        for (int a = 0; a < 4; a++)
            #pragma unroll
            for (int c = 0; c < 4; c++) sacc[a][c] = 0.f;
        #pragma unroll 4
        for (int d = 0; d < 128; d++) {
            float4 qv = *(const float4*)&QsT[d * QSTRIDE + i0];
            float4 kv = *(const float4*)&KVs[d * QSTRIDE + j0];
            float q[4] = {qv.x, qv.y, qv.z, qv.w};
            float k[4] = {kv.x, kv.y, kv.z, kv.w};
            #pragma unroll
            for (int a = 0; a < 4; a++)
                #pragma unroll
                for (int c = 0; c < 4; c++)
                    sacc[a][c] = fmaf(q[a], k[c], sacc[a][c]);
        }
        #pragma unroll
        for (int c = 0; c < 4; c++)
            #pragma unroll
            for (int a = 0; a < 4; a++)
                PsT[(j0 + c) * QSTRIDE + i0 + a] = sacc[a][c] * ATT_SCALE;
        __syncthreads();
        #pragma unroll
        for (int it = 0; it < 8; it++) {
            int idx = tid + it * 256;
            int j = idx >> 5; int d4 = (idx & 31) << 2;
            float4 v = *(const float4*)(qkv + base + (size_t)(kt * 64 + j) * C3 + 2 * Cc + h * Dd + d4);
            *(float4*)&KVs[j * VSTRIDE + d4] = v;
        }
        {
            int w = tid >> 5, lane = tid & 31;
            for (int rIt = 0; rIt < 8; rIt++) {
                int i = w * 8 + rIt;
                float s1 = PsT[lane * QSTRIDE + i];
                float s2 = PsT[(lane + 32) * QSTRIDE + i];
                float mx = fmaxf(s1, s2);
                #pragma unroll
                for (int o = 16; o; o >>= 1)
                    mx = fmaxf(mx, __shfl_xor_sync(0xffffffffu, mx, o));
                float m_old = m_s[i];
                float m_new = fmaxf(m_old, mx);
                float pp1 = __expf(s1 - m_new);
                float pp2 = __expf(s2 - m_new);
                PsT[lane * QSTRIDE + i] = pp1;
                PsT[(lane + 32) * QSTRIDE + i] = pp2;
                float ps = pp1 + pp2;
                #pragma unroll
                for (int o = 16; o; o >>= 1)
                    ps += __shfl_xor_sync(0xffffffffu, ps, o);
                if (lane == 0) {
                    float alpha = __expf(m_old - m_new);
                    l_s[i] = l_s[i] * alpha + ps;
                    m_s[i] = m_new;
                    al_s[i] = alpha;
                }
            }
        }
        __syncthreads();
        #pragma unroll
        for (int a = 0; a < 4; a++) {
            float alp = al_s[i0 + a];
            #pragma unroll
            for (int d = 0; d < 8; d++) accO[a][d] *= alp;
        }
        #pragma unroll 8
        for (int j = 0; j < 64; j++) {
            float4 pv = *(const float4*)&PsT[j * QSTRIDE + i0];
            float4 v0 = *(const float4*)&KVs[j * VSTRIDE + d0];
            float4 v1 = *(const float4*)&KVs[j * VSTRIDE + d0 + 4];
            float p[4] = {pv.x, pv.y, pv.z, pv.w};
            float vv[8] = {v0.x, v0.y, v0.z, v0.w, v1.x, v1.y, v1.z, v1.w};
            #pragma unroll
            for (int a = 0; a < 4; a++)
                #pragma unroll
                for (int d = 0; d < 8; d++)
                    accO[a][d] = fmaf(p[a], vv[d], accO[a][d]);
        }
    }
    #pragma unroll
    for (int a = 0; a < 4; a++) {
        int n = q0 + i0 + a;
        float invl = 1.f / l_s[i0 + a];
        float o8[8];
        #pragma unroll
        for (int d = 0; d < 8; d++) o8[d] = accO[a][d] * invl;
        uint32_t hp[4], lp[4];
        #pragma unroll
        for (int q = 0; q < 4; q++) split2(o8[2 * q], o8[2 * q + 1], hp[q], lp[q]);
        size_t off = ((size_t)b * Nn + n) * Cc + h * Dd + d0;
        *(uint4*)(out_hi + off) = make_uint4(hp[0], hp[1], hp[2], hp[3]);
        *(uint4*)(out_lo + off) = make_uint4(lp[0], lp[1], lp[2], lp[3]);
    }
}

// ================= host launcher =================
extern "C" void kernel_launch(void* const* d_in, const int* in_sizes, int n_in,
                              void* d_out, int out_size)
{
    const float* x       = (const float*)d_in[0];
    const float* ln1_g   = (const float*)d_in[1];
    const float* ln1_b   = (const float*)d_in[2];
    const float* w_qkv   = (const float*)d_in[3];
    const float* w_proj  = (const float*)d_in[4];
    const float* b_proj  = (const float*)d_in[5];
    const float* ln2_g   = (const float*)d_in[6];
    const float* ln2_b   = (const float*)d_in[7];
    const float* w1      = (const float*)d_in[8];
    const float* b1      = (const float*)d_in[9];
    const float* w2      = (const float*)d_in[10];
    const float* b2      = (const float*)d_in[11];
    const float* bn_g    = (const float*)d_in[12];
    const float* bn_b    = (const float*)d_in[13];
    const float* bn_mean = (const float*)d_in[14];
    const float* bn_var  = (const float*)d_in[15];
    float* out = (float*)d_out;

    float *p_qkv, *p_x1;
    __nv_bfloat16 *p_h_hi, *p_h_lo, *p_attn_hi, *p_attn_lo, *p_h1_hi, *p_h1_lo;
    __nv_bfloat16 *p_wqkv_hi, *p_wqkv_lo, *p_wproj_hi, *p_wproj_lo;
    __nv_bfloat16 *p_w1_hi, *p_w1_lo, *p_w2_hi, *p_w2_lo;
    cudaGetSymbolAddress((void**)&p_qkv,      g_qkv);
    cudaGetSymbolAddress((void**)&p_x1,       g_x1);
    cudaGetSymbolAddress((void**)&p_h_hi,     g_h_hi);
    cudaGetSymbolAddress((void**)&p_h_lo,     g_h_lo);
    cudaGetSymbolAddress((void**)&p_attn_hi,  g_attn_hi);
    cudaGetSymbolAddress((void**)&p_attn_lo,  g_attn_lo);
    cudaGetSymbolAddress((void**)&p_h1_hi,    g_h1_hi);
    cudaGetSymbolAddress((void**)&p_h1_lo,    g_h1_lo);
    cudaGetSymbolAddress((void**)&p_wqkv_hi,  g_wqkv_hi);
    cudaGetSymbolAddress((void**)&p_wqkv_lo,  g_wqkv_lo);
    cudaGetSymbolAddress((void**)&p_wproj_hi, g_wproj_hi);
    cudaGetSymbolAddress((void**)&p_wproj_lo, g_wproj_lo);
    cudaGetSymbolAddress((void**)&p_w1_hi,    g_w1_hi);
    cudaGetSymbolAddress((void**)&p_w1_lo,    g_w1_lo);
    cudaGetSymbolAddress((void**)&p_w2_hi,    g_w2_hi);
    cudaGetSymbolAddress((void**)&p_w2_lo,    g_w2_lo);

    cudaFuncSetAttribute(hgemm_k<0>, cudaFuncAttributeMaxDynamicSharedMemorySize, HG_SMEM);
    cudaFuncSetAttribute(hgemm_k<1>, cudaFuncAttributeMaxDynamicSharedMemorySize, HG_SMEM);
    cudaFuncSetAttribute(hgemm_k<2>, cudaFuncAttributeMaxDynamicSharedMemorySize, HG_SMEM);
    cudaFuncSetAttribute(hgemm_k<3>, cudaFuncAttributeMaxDynamicSharedMemorySize, HG_SMEM);

    // weight splits
    cvt_split_k<<<C3 * Cc / 1024, 256>>>(w_qkv,  p_wqkv_hi,  p_wqkv_lo);
    cvt_split_k<<<Cc * Cc / 1024, 256>>>(w_proj, p_wproj_hi, p_wproj_lo);
    cvt_split_k<<<Cc * Cc / 1024, 256>>>(w1,     p_w1_hi,    p_w1_lo);
    cvt_split_k<<<Cc * Cc / 1024, 256>>>(w2,     p_w2_hi,    p_w2_lo);

    // LN1 -> hi/lo
    layernorm_bf_k<<<Mm, 256>>>(x, ln1_g, ln1_b, p_h_hi, p_h_lo);

    // QKV GEMM (EPI 0, fp32 out)
    hgemm_k<0><<<dim3(C3 / 128, Mm / 128), 256, HG_SMEM>>>(
        p_h_hi, p_h_lo, p_wqkv_hi, p_wqkv_lo,
        p_qkv, nullptr, nullptr,
        nullptr, nullptr, nullptr, nullptr, nullptr, nullptr,
        C3, Cc);

    // Flash attention -> attn hi/lo
    int smem_bytes = (2 * 128 * QSTRIDE + 64 * QSTRIDE + 3 * 64) * (int)sizeof(float);
    cudaFuncSetAttribute(flash_k, cudaFuncAttributeMaxDynamicSharedMemorySize, smem_bytes);
    flash_k<<<dim3(Nn / 64, Bz * Hh), 256, smem_bytes>>>(p_qkv, p_attn_hi, p_attn_lo);

    // proj GEMM + bias + residual -> x1 fp32 (EPI 1)
    hgemm_k<1><<<dim3(Cc / 128, Mm / 128), 256, HG_SMEM>>>(
        p_attn_hi, p_attn_lo, p_wproj_hi, p_wproj_lo,
        p_x1, nullptr, nullptr,
        b_proj, x, nullptr, nullptr, nullptr, nullptr,
        Cc, Cc);

    // LN2 -> hi/lo
    layernorm_bf_k<<<Mm, 256>>>(p_x1, ln2_g, ln2_b, p_h_hi, p_h_lo);

    // MLP1: ELU(h @ w1^T + b1) -> h1 hi/lo (EPI 2)
    hgemm_k<2><<<dim3(Cc / 128, Mm / 128), 256, HG_SMEM>>>(
        p_h_hi, p_h_lo, p_w1_hi, p_w1_lo,
        nullptr, p_h1_hi, p_h1_lo,
        b1, nullptr, nullptr, nullptr, nullptr, nullptr,
        Cc, Cc);

    // MLP2: out = x1 + BN(ELU(h1 @ w2^T + b2)) (EPI 3)
    hgemm_k<3><<<dim3(Cc / 128, Mm / 128), 256, HG_SMEM>>>(
        p_h1_hi, p_h1_lo, p_w2_hi, p_w2_lo,
        out, nullptr, nullptr,
        b2, p_x1, bn_g, bn_b, bn_mean, bn_var,
        Cc, Cc);
}

// round 9
// speedup vs baseline: 3.4530x; 2.2673x over previous
#include <cuda_runtime.h>
#include <cuda_bf16.h>
#include <math.h>
#include <stdint.h>

// Problem constants
#define Bz   4
#define Nn   2048
#define Cc   1024
#define Hh   8
#define Dd   128
#define Mm   (Bz * Nn)          // 8192 tokens
#define C3   (3 * Cc)           // 3072
#define EPS  1e-5f
#define ATT_SCALE 0.08838834764831845f  // 128^-0.5

// ================= PTX helpers (plain sm_103-safe: sm_80-era features) ======
__device__ __forceinline__ uint32_t smem_u32(const void* p) {
    uint32_t a;
    asm("{ .reg .u64 t; cvta.to.shared.u64 t, %1; cvt.u32.u64 %0, t; }" : "=r"(a) : "l"(p));
    return a;
}
#define CP_ASYNC(dst, src) \
    asm volatile("cp.async.cg.shared.global [%0], [%1], 16;" :: "r"(dst), "l"(src))
#define CP_COMMIT() asm volatile("cp.async.commit_group;" ::: "memory")
#define CP_WAIT1()  asm volatile("cp.async.wait_group 1;" ::: "memory")
#define CP_WAIT0()  asm volatile("cp.async.wait_group 0;" ::: "memory")

__device__ __forceinline__ void ldsm_x4(uint32_t& r0, uint32_t& r1, uint32_t& r2, uint32_t& r3,
                                        uint32_t addr) {
    asm volatile("ldmatrix.sync.aligned.m8n8.x4.shared.b16 {%0,%1,%2,%3}, [%4];"
                 : "=r"(r0), "=r"(r1), "=r"(r2), "=r"(r3) : "r"(addr));
}
__device__ __forceinline__ void ldsm_x4_t(uint32_t& r0, uint32_t& r1, uint32_t& r2, uint32_t& r3,
                                          uint32_t addr) {
    asm volatile("ldmatrix.sync.aligned.m8n8.x4.trans.shared.b16 {%0,%1,%2,%3}, [%4];"
                 : "=r"(r0), "=r"(r1), "=r"(r2), "=r"(r3) : "r"(addr));
}
__device__ __forceinline__ void mma_bf16(float* d, const uint32_t* a, const uint32_t* b) {
    asm volatile(
        "mma.sync.aligned.m16n8k16.row.col.f32.bf16.bf16.f32 "
        "{%0,%1,%2,%3}, {%4,%5,%6,%7}, {%8,%9}, {%0,%1,%2,%3};"
        : "+f"(d[0]), "+f"(d[1]), "+f"(d[2]), "+f"(d[3])
        : "r"(a[0]), "r"(a[1]), "r"(a[2]), "r"(a[3]), "r"(b[0]), "r"(b[1]));
}

// hi/lo bf16 split of two floats packed into uint32 (elem0 in low half)
__device__ __forceinline__ void split2(float a, float b, uint32_t& hp, uint32_t& lp) {
    __nv_bfloat16 ha = __float2bfloat16(a), hb = __float2bfloat16(b);
    float ra = a - __bfloat162float(ha), rb = b - __bfloat162float(hb);
    __nv_bfloat16 la = __float2bfloat16(ra), lb = __float2bfloat16(rb);
    hp = (uint32_t)__bfloat16_as_ushort(ha) | ((uint32_t)__bfloat16_as_ushort(hb) << 16);
    lp = (uint32_t)__bfloat16_as_ushort(la) | ((uint32_t)__bfloat16_as_ushort(lb) << 16);
}
__device__ __forceinline__ uint32_t cvt2bf(float a, float b) {
    __nv_bfloat162 t = __floats2bfloat162_rn(a, b);   // .x = a (low), .y = b (high)
    return *(uint32_t*)&t;
}

// ================= scratch (device globals) =================
__device__ float g_x1 [Mm * Cc];
__device__ __nv_bfloat16 g_qkv_hi[Mm * C3], g_qkv_lo[Mm * C3];
__device__ __nv_bfloat16 g_h_hi   [Mm * Cc], g_h_lo   [Mm * Cc];
__device__ __nv_bfloat16 g_attn_hi[Mm * Cc], g_attn_lo[Mm * Cc];
__device__ __nv_bfloat16 g_h1_hi  [Mm * Cc], g_h1_lo  [Mm * Cc];
__device__ __nv_bfloat16 g_wqkv_hi [C3 * Cc], g_wqkv_lo [C3 * Cc];
__device__ __nv_bfloat16 g_wproj_hi[Cc * Cc], g_wproj_lo[Cc * Cc];
__device__ __nv_bfloat16 g_w1_hi   [Cc * Cc], g_w1_lo   [Cc * Cc];
__device__ __nv_bfloat16 g_w2_hi   [Cc * Cc], g_w2_lo   [Cc * Cc];

// ================= fp32 -> bf16 hi/lo converter =================
__global__ void cvt_split_k(const float* __restrict__ w,
                            __nv_bfloat16* __restrict__ hi, __nv_bfloat16* __restrict__ lo)
{
    int i = blockIdx.x * 256 + threadIdx.x;
    float4 v = ((const float4*)w)[i];
    uint32_t h0, l0, h1, l1;
    split2(v.x, v.y, h0, l0);
    split2(v.z, v.w, h1, l1);
    ((uint2*)hi)[i] = make_uint2(h0, h1);
    ((uint2*)lo)[i] = make_uint2(l0, l1);
}

// ================= LayerNorm -> bf16 hi/lo =================
__global__ void layernorm_bf_k(const float* __restrict__ in, const float* __restrict__ g,
                               const float* __restrict__ b,
                               __nv_bfloat16* __restrict__ hi, __nv_bfloat16* __restrict__ lo)
{
    int row = blockIdx.x;
    int t = threadIdx.x;
    const float4* inr = (const float4*)(in + (size_t)row * Cc);
    float4 v = inr[t];
    float s  = v.x + v.y + v.z + v.w;
    float ss = v.x*v.x + v.y*v.y + v.z*v.z + v.w*v.w;
    #pragma unroll
    for (int o = 16; o; o >>= 1) {
        s  += __shfl_xor_sync(0xffffffffu, s,  o);
        ss += __shfl_xor_sync(0xffffffffu, ss, o);
    }
    __shared__ float sm1[8], sm2[8];
    if ((t & 31) == 0) { sm1[t >> 5] = s; sm2[t >> 5] = ss; }
    __syncthreads();
    if (t < 32) {
        s  = (t < 8) ? sm1[t] : 0.f;
        ss = (t < 8) ? sm2[t] : 0.f;
        #pragma unroll
        for (int o = 4; o; o >>= 1) {
            s  += __shfl_xor_sync(0xffffffffu, s,  o);
            ss += __shfl_xor_sync(0xffffffffu, ss, o);
        }
        if (t == 0) { sm1[0] = s; sm2[0] = ss; }
    }
    __syncthreads();
    float mu  = sm1[0] * (1.f / Cc);
    float var = sm2[0] * (1.f / Cc) - mu * mu;
    float inv = rsqrtf(var + EPS);
    float4 gv = ((const float4*)g)[t];
    float4 bv = ((const float4*)b)[t];
    float o0 = (v.x - mu) * inv * gv.x + bv.x;
    float o1 = (v.y - mu) * inv * gv.y + bv.y;
    float o2 = (v.z - mu) * inv * gv.z + bv.z;
    float o3 = (v.w - mu) * inv * gv.w + bv.w;
    uint32_t h0, l0, h1, l1;
    split2(o0, o1, h0, l0);
    split2(o2, o3, h1, l1);
    ((uint2*)(hi + (size_t)row * Cc))[t] = make_uint2(h0, h1);
    ((uint2*)(lo + (size_t)row * Cc))[t] = make_uint2(l0, l1);
}

// ================= mma.sync split-bf16 GEMM =================
// C[M,N] = A[M,K] @ B[N,K]^T via AhiBhi + AhiBlo + AloBhi, fp32 accum.
// EPI: 0 fp32 | 1 +bias+res fp32 | 2 +bias,ELU->bf16 split | 3 +bias,ELU,BN,+res fp32
// EPI 4: plain -> bf16 hi/lo split (no bias)
#define BK      64
#define SSTRIDE 72
#define TILE_B  (128 * SSTRIDE * 2)
#define STAGE_B (4 * TILE_B)
#define HG_SMEM (2 * STAGE_B)

template <int EPI>
__global__ __launch_bounds__(256, 1)
void hgemm_k(const __nv_bfloat16* __restrict__ Ahi, const __nv_bfloat16* __restrict__ Alo,
             const __nv_bfloat16* __restrict__ Bhi, const __nv_bfloat16* __restrict__ Blo,
             float* __restrict__ Cf, __nv_bfloat16* __restrict__ Chi, __nv_bfloat16* __restrict__ Clo,
             const float* __restrict__ bias, const float* __restrict__ res,
             const float* __restrict__ bng, const float* __restrict__ bnb,
             const float* __restrict__ bnm, const float* __restrict__ bnv,
             int Ndim, int Kdim)
{
    extern __shared__ char dsm[];
    const int tid = threadIdx.x;
    const int wid = tid >> 5, lid = tid & 31;
    const int m_blk = blockIdx.y * 128, n_blk = blockIdx.x * 128;
    const int wm = wid & 3, wn = wid >> 2;

    const uint32_t sbase = smem_u32(dsm);

    float acc[2][8][4];
    #pragma unroll
    for (int i = 0; i < 2; i++)
        #pragma unroll
        for (int j = 0; j < 8; j++)
            #pragma unroll
            for (int q = 0; q < 4; q++) acc[i][j][q] = 0.f;

    const int a_row = 32 * wm + (lid & 15);
    const int a_col = (lid >> 4) * 8;
    const int b_row = 64 * wn + ((lid & 16) >> 1) + (lid & 7);
    const int b_col = (lid & 8);

    auto load_stage = [&](int c) {
        const int kk = c * BK;
        const uint32_t sb = sbase + (c & 1) * STAGE_B;
        #pragma unroll
        for (int it = 0; it < 4; ++it) {
            int id = tid + it * 256;
            int row = id >> 3, seg = id & 7;
            uint32_t so = (uint32_t)(row * SSTRIDE + seg * 8) * 2;
            size_t ga = (size_t)(m_blk + row) * Kdim + kk + seg * 8;
            size_t gb = (size_t)(n_blk + row) * Kdim + kk + seg * 8;
            CP_ASYNC(sb + so,              Ahi + ga);
            CP_ASYNC(sb + TILE_B + so,     Alo + ga);
            CP_ASYNC(sb + 2 * TILE_B + so, Bhi + gb);
            CP_ASYNC(sb + 3 * TILE_B + so, Blo + gb);
        }
        CP_COMMIT();
    };

    const int nchunk = Kdim / BK;
    load_stage(0);
    for (int c = 0; c < nchunk; ++c) {
        if (c + 1 < nchunk) { load_stage(c + 1); CP_WAIT1(); }
        else                { CP_WAIT0(); }
        __syncthreads();
        const uint32_t sb = sbase + (c & 1) * STAGE_B;
        #pragma unroll
        for (int k16 = 0; k16 < BK / 16; ++k16) {
            uint32_t ah[2][4], al[2][4], bh[8][2], bl[8][2];
            #pragma unroll
            for (int i = 0; i < 2; ++i) {
                uint32_t ao = sb + (uint32_t)((a_row + 16 * i) * SSTRIDE + a_col + 16 * k16) * 2;
                ldsm_x4(ah[i][0], ah[i][1], ah[i][2], ah[i][3], ao);
                ldsm_x4(al[i][0], al[i][1], al[i][2], al[i][3], ao + TILE_B);
            }
            #pragma unroll
            for (int jj = 0; jj < 4; ++jj) {
                uint32_t bo = sb + 2 * TILE_B
                            + (uint32_t)((b_row + 16 * jj) * SSTRIDE + b_col + 16 * k16) * 2;
                ldsm_x4(bh[2*jj][0], bh[2*jj][1], bh[2*jj+1][0], bh[2*jj+1][1], bo);
                ldsm_x4(bl[2*jj][0], bl[2*jj][1], bl[2*jj+1][0], bl[2*jj+1][1], bo + TILE_B);
            }
            #pragma unroll
            for (int i = 0; i < 2; ++i)
                #pragma unroll
                for (int j = 0; j < 8; ++j) {
                    mma_bf16(acc[i][j], ah[i], bh[j]);
                    mma_bf16(acc[i][j], ah[i], bl[j]);
                    mma_bf16(acc[i][j], al[i], bh[j]);
                }
        }
        __syncthreads();
    }

    #pragma unroll
    for (int i = 0; i < 2; ++i) {
        #pragma unroll
        for (int half = 0; half < 2; ++half) {
            const int r = m_blk + 32 * wm + 16 * i + (lid >> 2) + 8 * half;
            #pragma unroll
            for (int j = 0; j < 8; ++j) {
                const int c = n_blk + 64 * wn + 8 * j + 2 * (lid & 3);
                float v0 = acc[i][j][2 * half + 0];
                float v1 = acc[i][j][2 * half + 1];
                if (EPI == 1) {
                    const float2 rv = *(const float2*)(res + (size_t)r * Ndim + c);
                    v0 += __ldg(bias + c)     + rv.x;
                    v1 += __ldg(bias + c + 1) + rv.y;
                } else if (EPI == 2) {
                    v0 += __ldg(bias + c);
                    v1 += __ldg(bias + c + 1);
                    v0 = (v0 > 0.f) ? v0 : expm1f(v0);
                    v1 = (v1 > 0.f) ? v1 : expm1f(v1);
                } else if (EPI == 3) {
                    const float2 rv = *(const float2*)(res + (size_t)r * Ndim + c);
                    v0 += __ldg(bias + c);
                    v1 += __ldg(bias + c + 1);
                    v0 = (v0 > 0.f) ? v0 : expm1f(v0);
                    v1 = (v1 > 0.f) ? v1 : expm1f(v1);
                    v0 = (v0 - __ldg(bnm + c))     * rsqrtf(__ldg(bnv + c) + EPS)     * __ldg(bng + c)     + __ldg(bnb + c)     + rv.x;
                    v1 = (v1 - __ldg(bnm + c + 1)) * rsqrtf(__ldg(bnv + c + 1) + EPS) * __ldg(bng + c + 1) + __ldg(bnb + c + 1) + rv.y;
                }
                if (EPI == 2 || EPI == 4) {
                    uint32_t hp, lp;
                    split2(v0, v1, hp, lp);
                    *(uint32_t*)(Chi + (size_t)r * Ndim + c) = hp;
                    *(uint32_t*)(Clo + (size_t)r * Ndim + c) = lp;
                } else {
                    *(float2*)(Cf + (size_t)r * Ndim + c) = make_float2(v0, v1);
                }
            }
        }
    }
}

// ================= Tensor-core flash attention (bf16, QK split) =================
// BQ=128, BK=64, 8 warps x 16 q-rows. Q hi/lo resident; K hi/lo + V double-buffered.
#define FQSTR     136                      // bf16 elems per smem row (128 + 8)
#define FQ_B      (128 * FQSTR * 2)        // 34816 bytes per Q buffer
#define FK_B      (64 * FQSTR * 2)         // 17408 bytes per K/V tile
#define FSTAGE_B  (3 * FK_B)               // Khi | Klo | V
#define FLASH_SMEM (2 * FQ_B + 2 * FSTAGE_B)  // 174080

__global__ __launch_bounds__(256, 1)
void flash_tc_k(const __nv_bfloat16* __restrict__ qkv_hi,
                const __nv_bfloat16* __restrict__ qkv_lo,
                __nv_bfloat16* __restrict__ out_hi, __nv_bfloat16* __restrict__ out_lo)
{
    extern __shared__ char fsm[];
    const int tid = threadIdx.x, wid = tid >> 5, lid = tid & 31;
    const int bh = blockIdx.y, b = bh >> 3, h = bh & 7;
    const int q0 = blockIdx.x * 128;
    const size_t base = (size_t)b * Nn * C3 + h * Dd;

    const uint32_t sQhi = smem_u32(fsm);
    const uint32_t sQlo = sQhi + FQ_B;
    const uint32_t sKV  = sQlo + FQ_B;

    // ---- Q loads (hi+lo), 128 rows x 16 segs of 16B each ----
    #pragma unroll
    for (int it = 0; it < 8; ++it) {
        int idx = tid + it * 256;
        int row = idx >> 4, seg = idx & 15;
        uint32_t so = (uint32_t)row * (FQSTR * 2) + seg * 16;
        size_t g = base + (size_t)(q0 + row) * C3 + seg * 8;
        CP_ASYNC(sQhi + so, qkv_hi + g);
        CP_ASYNC(sQlo + so, qkv_lo + g);
    }

    auto load_kv = [&](int kt) {
        const uint32_t sb = sKV + (kt & 1) * FSTAGE_B;
        #pragma unroll
        for (int it = 0; it < 4; ++it) {
            int idx = tid + it * 256;
            int row = idx >> 4, seg = idx & 15;
            uint32_t so = (uint32_t)row * (FQSTR * 2) + seg * 16;
            size_t gk = base + (size_t)(kt * 64 + row) * C3 + Cc + seg * 8;
            size_t gv = base + (size_t)(kt * 64 + row) * C3 + 2 * Cc + seg * 8;
            CP_ASYNC(sb + so,              qkv_hi + gk);
            CP_ASYNC(sb + FK_B + so,       qkv_lo + gk);
            CP_ASYNC(sb + 2 * FK_B + so,   qkv_hi + gv);
        }
        CP_COMMIT();
    };

    load_kv(0);   // commit bundles Q loads too

    // state
    const float SCL = ATT_SCALE * 1.4426950408889634f;  // scale * log2(e)
    float m0 = -1e30f, m1 = -1e30f, l0 = 0.f, l1 = 0.f;
    float accO[16][4];
    #pragma unroll
    for (int j = 0; j < 16; ++j)
        #pragma unroll
        for (int q = 0; q < 4; ++q) accO[j][q] = 0.f;

    // fragment addressing
    const uint32_t a_off0 = (uint32_t)((16 * wid + (lid & 15)) * FQSTR + (lid >> 4) * 8) * 2;
    const int b_rl = ((lid & 16) >> 1) + (lid & 7);   // K frag row-in-tile
    const int b_cl = (lid & 8);
    const int v_rl = (lid & 8) + (lid & 7);           // V trans frag row-in-tile
    const int v_cl = ((lid & 16) >> 1);

    const int NT = Nn / 64;
    for (int kt = 0; kt < NT; ++kt) {
        if (kt + 1 < NT) { load_kv(kt + 1); CP_WAIT1(); }
        else             { CP_WAIT0(); }
        __syncthreads();
        const uint32_t sb = sKV + (kt & 1) * FSTAGE_B;

        // ---- S = Q K^T (3-term split) ----
        float accS[8][4];
        #pragma unroll
        for (int j = 0; j < 8; ++j)
            #pragma unroll
            for (int q = 0; q < 4; ++q) accS[j][q] = 0.f;

        #pragma unroll
        for (int k16 = 0; k16 < 8; ++k16) {
            uint32_t ah[4], al[4];
            uint32_t ao = sQhi + a_off0 + (uint32_t)(16 * k16) * 2;
            ldsm_x4(ah[0], ah[1], ah[2], ah[3], ao);
            ldsm_x4(al[0], al[1], al[2], al[3], ao + FQ_B);
            #pragma unroll
            for (int jj = 0; jj < 4; ++jj) {
                uint32_t bh[2][2], bl[2][2];
                uint32_t bo = sb + (uint32_t)((16 * jj + b_rl) * FQSTR + b_cl + 16 * k16) * 2;
                ldsm_x4(bh[0][0], bh[0][1], bh[1][0], bh[1][1], bo);
                ldsm_x4(bl[0][0], bl[0][1], bl[1][0], bl[1][1], bo + FK_B);
                #pragma unroll
                for (int t = 0; t < 2; ++t) {
                    mma_bf16(accS[2*jj+t], ah, bh[t]);
                    mma_bf16(accS[2*jj+t], ah, bl[t]);
                    mma_bf16(accS[2*jj+t], al, bh[t]);
                }
            }
        }

        // ---- online softmax (rows r0 = lid>>2, r1 = r0+8 of this warp's 16) ----
        float mx0 = -1e30f, mx1 = -1e30f;
        #pragma unroll
        for (int j = 0; j < 8; ++j) {
            mx0 = fmaxf(mx0, fmaxf(accS[j][0], accS[j][1]));
            mx1 = fmaxf(mx1, fmaxf(accS[j][2], accS[j][3]));
        }
        mx0 = fmaxf(mx0, __shfl_xor_sync(0xffffffffu, mx0, 1));
        mx0 = fmaxf(mx0, __shfl_xor_sync(0xffffffffu, mx0, 2));
        mx1 = fmaxf(mx1, __shfl_xor_sync(0xffffffffu, mx1, 1));
        mx1 = fmaxf(mx1, __shfl_xor_sync(0xffffffffu, mx1, 2));
        mx0 *= SCL; mx1 *= SCL;
        float mn0 = fmaxf(m0, mx0), mn1 = fmaxf(m1, mx1);
        float al0 = exp2f(m0 - mn0), al1 = exp2f(m1 - mn1);
        m0 = mn0; m1 = mn1;

        float ls0 = 0.f, ls1 = 0.f;
        #pragma unroll
        for (int j = 0; j < 8; ++j) {
            float p0 = exp2f(accS[j][0] * SCL - mn0);
            float p1 = exp2f(accS[j][1] * SCL - mn0);
            float p2 = exp2f(accS[j][2] * SCL - mn1);
            float p3 = exp2f(accS[j][3] * SCL - mn1);
            accS[j][0] = p0; accS[j][1] = p1; accS[j][2] = p2; accS[j][3] = p3;
            ls0 += p0 + p1; ls1 += p2 + p3;
        }
        ls0 += __shfl_xor_sync(0xffffffffu, ls0, 1);
        ls0 += __shfl_xor_sync(0xffffffffu, ls0, 2);
        ls1 += __shfl_xor_sync(0xffffffffu, ls1, 1);
        ls1 += __shfl_xor_sync(0xffffffffu, ls1, 2);
        l0 = l0 * al0 + ls0;
        l1 = l1 * al1 + ls1;

        #pragma unroll
        for (int j = 0; j < 16; ++j) {
            accO[j][0] *= al0; accO[j][1] *= al0;
            accO[j][2] *= al1; accO[j][3] *= al1;
        }

        // ---- P a-fragments (bf16) ----
        uint32_t pa[4][4];
        #pragma unroll
        for (int kk = 0; kk < 4; ++kk) {
            pa[kk][0] = cvt2bf(accS[2*kk][0],   accS[2*kk][1]);
            pa[kk][1] = cvt2bf(accS[2*kk][2],   accS[2*kk][3]);
            pa[kk][2] = cvt2bf(accS[2*kk+1][0], accS[2*kk+1][1]);
            pa[kk][3] = cvt2bf(accS[2*kk+1][2], accS[2*kk+1][3]);
        }

        // ---- O += P V ----
        #pragma unroll
        for (int kk = 0; kk < 4; ++kk) {
            #pragma unroll
            for (int jj = 0; jj < 8; ++jj) {
                uint32_t r0, r1, r2, r3;
                uint32_t vo = sb + 2 * FK_B
                            + (uint32_t)((16 * kk + v_rl) * FQSTR + 16 * jj + v_cl) * 2;
                ldsm_x4_t(r0, r1, r2, r3, vo);
                uint32_t vb0[2] = {r0, r1}, vb1[2] = {r2, r3};
                mma_bf16(accO[2*jj],     pa[kk], vb0);
                mma_bf16(accO[2*jj + 1], pa[kk], vb1);
            }
        }
        __syncthreads();
    }

    // ---- epilogue ----
    float inv0 = 1.f / l0, inv1 = 1.f / l1;
    const int row0 = q0 + 16 * wid + (lid >> 2);
    #pragma unroll
    for (int j = 0; j < 16; ++j) {
        const int col = h * Dd + 8 * j + 2 * (lid & 3);
        uint32_t hp, lp;
        split2(accO[j][0] * inv0, accO[j][1] * inv0, hp, lp);
        size_t o0 = ((size_t)b * Nn + row0) * Cc + col;
        *(uint32_t*)(out_hi + o0) = hp;
        *(uint32_t*)(out_lo + o0) = lp;
        split2(accO[j][2] * inv1, accO[j][3] * inv1, hp, lp);
        size_t o1 = ((size_t)b * Nn + row0 + 8) * Cc + col;
        *(uint32_t*)(out_hi + o1) = hp;
        *(uint32_t*)(out_lo + o1) = lp;
    }
}

// ================= host launcher =================
extern "C" void kernel_launch(void* const* d_in, const int* in_sizes, int n_in,
                              void* d_out, int out_size)
{
    const float* x       = (const float*)d_in[0];
    const float* ln1_g   = (const float*)d_in[1];
    const float* ln1_b   = (const float*)d_in[2];
    const float* w_qkv   = (const float*)d_in[3];
    const float* w_proj  = (const float*)d_in[4];
    const float* b_proj  = (const float*)d_in[5];
    const float* ln2_g   = (const float*)d_in[6];
    const float* ln2_b   = (const float*)d_in[7];
    const float* w1      = (const float*)d_in[8];
    const float* b1      = (const float*)d_in[9];
    const float* w2      = (const float*)d_in[10];
    const float* b2      = (const float*)d_in[11];
    const float* bn_g    = (const float*)d_in[12];
    const float* bn_b    = (const float*)d_in[13];
    const float* bn_mean = (const float*)d_in[14];
    const float* bn_var  = (const float*)d_in[15];
    float* out = (float*)d_out;

    float *p_x1;
    __nv_bfloat16 *p_qkv_hi, *p_qkv_lo;
    __nv_bfloat16 *p_h_hi, *p_h_lo, *p_attn_hi, *p_attn_lo, *p_h1_hi, *p_h1_lo;
    __nv_bfloat16 *p_wqkv_hi, *p_wqkv_lo, *p_wproj_hi, *p_wproj_lo;
    __nv_bfloat16 *p_w1_hi, *p_w1_lo, *p_w2_hi, *p_w2_lo;
    cudaGetSymbolAddress((void**)&p_x1,       g_x1);
    cudaGetSymbolAddress((void**)&p_qkv_hi,   g_qkv_hi);
    cudaGetSymbolAddress((void**)&p_qkv_lo,   g_qkv_lo);
    cudaGetSymbolAddress((void**)&p_h_hi,     g_h_hi);
    cudaGetSymbolAddress((void**)&p_h_lo,     g_h_lo);
    cudaGetSymbolAddress((void**)&p_attn_hi,  g_attn_hi);
    cudaGetSymbolAddress((void**)&p_attn_lo,  g_attn_lo);
    cudaGetSymbolAddress((void**)&p_h1_hi,    g_h1_hi);
    cudaGetSymbolAddress((void**)&p_h1_lo,    g_h1_lo);
    cudaGetSymbolAddress((void**)&p_wqkv_hi,  g_wqkv_hi);
    cudaGetSymbolAddress((void**)&p_wqkv_lo,  g_wqkv_lo);
    cudaGetSymbolAddress((void**)&p_wproj_hi, g_wproj_hi);
    cudaGetSymbolAddress((void**)&p_wproj_lo, g_wproj_lo);
    cudaGetSymbolAddress((void**)&p_w1_hi,    g_w1_hi);
    cudaGetSymbolAddress((void**)&p_w1_lo,    g_w1_lo);
    cudaGetSymbolAddress((void**)&p_w2_hi,    g_w2_hi);
    cudaGetSymbolAddress((void**)&p_w2_lo,    g_w2_lo);

    cudaFuncSetAttribute(hgemm_k<1>, cudaFuncAttributeMaxDynamicSharedMemorySize, HG_SMEM);
    cudaFuncSetAttribute(hgemm_k<2>, cudaFuncAttributeMaxDynamicSharedMemorySize, HG_SMEM);
    cudaFuncSetAttribute(hgemm_k<3>, cudaFuncAttributeMaxDynamicSharedMemorySize, HG_SMEM);
    cudaFuncSetAttribute(hgemm_k<4>, cudaFuncAttributeMaxDynamicSharedMemorySize, HG_SMEM);
    cudaFuncSetAttribute(flash_tc_k, cudaFuncAttributeMaxDynamicSharedMemorySize, FLASH_SMEM);

    // weight splits
    cvt_split_k<<<C3 * Cc / 1024, 256>>>(w_qkv,  p_wqkv_hi,  p_wqkv_lo);
    cvt_split_k<<<Cc * Cc / 1024, 256>>>(w_proj, p_wproj_hi, p_wproj_lo);
    cvt_split_k<<<Cc * Cc / 1024, 256>>>(w1,     p_w1_hi,    p_w1_lo);
    cvt_split_k<<<Cc * Cc / 1024, 256>>>(w2,     p_w2_hi,    p_w2_lo);

    // LN1 -> hi/lo
    layernorm_bf_k<<<Mm, 256>>>(x, ln1_g, ln1_b, p_h_hi, p_h_lo);

    // QKV GEMM -> bf16 hi/lo split (EPI 4)
    hgemm_k<4><<<dim3(C3 / 128, Mm / 128), 256, HG_SMEM>>>(
        p_h_hi, p_h_lo, p_wqkv_hi, p_wqkv_lo,
        nullptr, p_qkv_hi, p_qkv_lo,
        nullptr, nullptr, nullptr, nullptr, nullptr, nullptr,
        C3, Cc);

    // Tensor-core flash attention -> attn hi/lo
    flash_tc_k<<<dim3(Nn / 128, Bz * Hh), 256, FLASH_SMEM>>>(
        p_qkv_hi, p_qkv_lo, p_attn_hi, p_attn_lo);

    // proj GEMM + bias + residual -> x1 fp32 (EPI 1)
    hgemm_k<1><<<dim3(Cc / 128, Mm / 128), 256, HG_SMEM>>>(
        p_attn_hi, p_attn_lo, p_wproj_hi, p_wproj_lo,
        p_x1, nullptr, nullptr,
        b_proj, x, nullptr, nullptr, nullptr, nullptr,
        Cc, Cc);

    // LN2 -> hi/lo
    layernorm_bf_k<<<Mm, 256>>>(p_x1, ln2_g, ln2_b, p_h_hi, p_h_lo);

    // MLP1: ELU(h @ w1^T + b1) -> h1 hi/lo (EPI 2)
    hgemm_k<2><<<dim3(Cc / 128, Mm / 128), 256, HG_SMEM>>>(
        p_h_hi, p_h_lo, p_w1_hi, p_w1_lo,
        nullptr, p_h1_hi, p_h1_lo,
        b1, nullptr, nullptr, nullptr, nullptr, nullptr,
        Cc, Cc);

    // MLP2: out = x1 + BN(ELU(h1 @ w2^T + b2)) (EPI 3)
    hgemm_k<3><<<dim3(Cc / 128, Mm / 128), 256, HG_SMEM>>>(
        p_h1_hi, p_h1_lo, p_w2_hi, p_w2_lo,
        out, nullptr, nullptr,
        b2, p_x1, bn_g, bn_b, bn_mean, bn_var,
        Cc, Cc);
}

// round 11
// speedup vs baseline: 3.7375x; 1.0824x over previous
#include <cuda_runtime.h>
#include <cuda_bf16.h>
#include <math.h>
#include <stdint.h>

// Problem constants
#define Bz   4
#define Nn   2048
#define Cc   1024
#define Hh   8
#define Dd   128
#define Mm   (Bz * Nn)          // 8192 tokens
#define C3   (3 * Cc)           // 3072
#define EPS  1e-5f
#define ATT_SCALE 0.08838834764831845f  // 128^-0.5

// ================= PTX helpers =================
__device__ __forceinline__ uint32_t smem_u32(const void* p) {
    uint32_t a;
    asm("{ .reg .u64 t; cvta.to.shared.u64 t, %1; cvt.u32.u64 %0, t; }" : "=r"(a) : "l"(p));
    return a;
}
#define CP_ASYNC(dst, src) \
    asm volatile("cp.async.cg.shared.global [%0], [%1], 16;" :: "r"(dst), "l"(src))
#define CP_COMMIT() asm volatile("cp.async.commit_group;" ::: "memory")
#define CP_WAIT1()  asm volatile("cp.async.wait_group 1;" ::: "memory")
#define CP_WAIT0()  asm volatile("cp.async.wait_group 0;" ::: "memory")

__device__ __forceinline__ void ldsm_x4(uint32_t& r0, uint32_t& r1, uint32_t& r2, uint32_t& r3,
                                        uint32_t addr) {
    asm volatile("ldmatrix.sync.aligned.m8n8.x4.shared.b16 {%0,%1,%2,%3}, [%4];"
                 : "=r"(r0), "=r"(r1), "=r"(r2), "=r"(r3) : "r"(addr));
}
__device__ __forceinline__ void ldsm_x4_t(uint32_t& r0, uint32_t& r1, uint32_t& r2, uint32_t& r3,
                                          uint32_t addr) {
    asm volatile("ldmatrix.sync.aligned.m8n8.x4.trans.shared.b16 {%0,%1,%2,%3}, [%4];"
                 : "=r"(r0), "=r"(r1), "=r"(r2), "=r"(r3) : "r"(addr));
}
__device__ __forceinline__ void mma_bf16(float* d, const uint32_t* a, const uint32_t* b) {
    asm volatile(
        "mma.sync.aligned.m16n8k16.row.col.f32.bf16.bf16.f32 "
        "{%0,%1,%2,%3}, {%4,%5,%6,%7}, {%8,%9}, {%0,%1,%2,%3};"
        : "+f"(d[0]), "+f"(d[1]), "+f"(d[2]), "+f"(d[3])
        : "r"(a[0]), "r"(a[1]), "r"(a[2]), "r"(a[3]), "r"(b[0]), "r"(b[1]));
}

__device__ __forceinline__ void split2(float a, float b, uint32_t& hp, uint32_t& lp) {
    __nv_bfloat16 ha = __float2bfloat16(a), hb = __float2bfloat16(b);
    float ra = a - __bfloat162float(ha), rb = b - __bfloat162float(hb);
    __nv_bfloat16 la = __float2bfloat16(ra), lb = __float2bfloat16(rb);
    hp = (uint32_t)__bfloat16_as_ushort(ha) | ((uint32_t)__bfloat16_as_ushort(hb) << 16);
    lp = (uint32_t)__bfloat16_as_ushort(la) | ((uint32_t)__bfloat16_as_ushort(lb) << 16);
}
__device__ __forceinline__ uint32_t cvt2bf(float a, float b) {
    __nv_bfloat162 t = __floats2bfloat162_rn(a, b);
    return *(uint32_t*)&t;
}

// ================= scratch (device globals) =================
__device__ float g_x1 [Mm * Cc];
__device__ __nv_bfloat16 g_qkv_hi[Mm * C3], g_qkv_lo[Mm * C3];
__device__ __nv_bfloat16 g_h_hi   [Mm * Cc], g_h_lo   [Mm * Cc];
__device__ __nv_bfloat16 g_attn_hi[Mm * Cc], g_attn_lo[Mm * Cc];
__device__ __nv_bfloat16 g_h1_hi  [Mm * Cc], g_h1_lo  [Mm * Cc];
__device__ __nv_bfloat16 g_wqkv_hi [C3 * Cc], g_wqkv_lo [C3 * Cc];
__device__ __nv_bfloat16 g_wproj_hi[Cc * Cc], g_wproj_lo[Cc * Cc];
__device__ __nv_bfloat16 g_w1_hi   [Cc * Cc], g_w1_lo   [Cc * Cc];
__device__ __nv_bfloat16 g_w2_hi   [Cc * Cc], g_w2_lo   [Cc * Cc];

// ================= fused fp32 -> bf16 hi/lo converter (all 4 weights) ========
// blocks [0,3072): w_qkv ; [3072,4096): w_proj ; [4096,5120): w1 ; [5120,6144): w2
__global__ void cvt_split_all_k(const float* __restrict__ wqkv, const float* __restrict__ wproj,
                                const float* __restrict__ w1, const float* __restrict__ w2,
                                __nv_bfloat16* __restrict__ qkv_hi, __nv_bfloat16* __restrict__ qkv_lo,
                                __nv_bfloat16* __restrict__ proj_hi, __nv_bfloat16* __restrict__ proj_lo,
                                __nv_bfloat16* __restrict__ w1_hi, __nv_bfloat16* __restrict__ w1_lo,
                                __nv_bfloat16* __restrict__ w2_hi, __nv_bfloat16* __restrict__ w2_lo)
{
    int blk = blockIdx.x;
    const float* src;
    __nv_bfloat16 *hi, *lo;
    int local;
    if (blk < 3072)      { src = wqkv;  hi = qkv_hi;  lo = qkv_lo;  local = blk; }
    else if (blk < 4096) { src = wproj; hi = proj_hi; lo = proj_lo; local = blk - 3072; }
    else if (blk < 5120) { src = w1;    hi = w1_hi;   lo = w1_lo;   local = blk - 4096; }
    else                 { src = w2;    hi = w2_hi;   lo = w2_lo;   local = blk - 5120; }
    int i = local * 256 + threadIdx.x;
    float4 v = ((const float4*)src)[i];
    uint32_t h0, l0, h1, l1;
    split2(v.x, v.y, h0, l0);
    split2(v.z, v.w, h1, l1);
    ((uint2*)hi)[i] = make_uint2(h0, h1);
    ((uint2*)lo)[i] = make_uint2(l0, l1);
}

// ================= LayerNorm -> bf16 hi/lo =================
__global__ void layernorm_bf_k(const float* __restrict__ in, const float* __restrict__ g,
                               const float* __restrict__ b,
                               __nv_bfloat16* __restrict__ hi, __nv_bfloat16* __restrict__ lo)
{
    int row = blockIdx.x;
    int t = threadIdx.x;
    const float4* inr = (const float4*)(in + (size_t)row * Cc);
    float4 v = inr[t];
    float s  = v.x + v.y + v.z + v.w;
    float ss = v.x*v.x + v.y*v.y + v.z*v.z + v.w*v.w;
    #pragma unroll
    for (int o = 16; o; o >>= 1) {
        s  += __shfl_xor_sync(0xffffffffu, s,  o);
        ss += __shfl_xor_sync(0xffffffffu, ss, o);
    }
    __shared__ float sm1[8], sm2[8];
    if ((t & 31) == 0) { sm1[t >> 5] = s; sm2[t >> 5] = ss; }
    __syncthreads();
    if (t < 32) {
        s  = (t < 8) ? sm1[t] : 0.f;
        ss = (t < 8) ? sm2[t] : 0.f;
        #pragma unroll
        for (int o = 4; o; o >>= 1) {
            s  += __shfl_xor_sync(0xffffffffu, s,  o);
            ss += __shfl_xor_sync(0xffffffffu, ss, o);
        }
        if (t == 0) { sm1[0] = s; sm2[0] = ss; }
    }
    __syncthreads();
    float mu  = sm1[0] * (1.f / Cc);
    float var = sm2[0] * (1.f / Cc) - mu * mu;
    float inv = rsqrtf(var + EPS);
    float4 gv = ((const float4*)g)[t];
    float4 bv = ((const float4*)b)[t];
    float o0 = (v.x - mu) * inv * gv.x + bv.x;
    float o1 = (v.y - mu) * inv * gv.y + bv.y;
    float o2 = (v.z - mu) * inv * gv.z + bv.z;
    float o3 = (v.w - mu) * inv * gv.w + bv.w;
    uint32_t h0, l0, h1, l1;
    split2(o0, o1, h0, l0);
    split2(o2, o3, h1, l1);
    ((uint2*)(hi + (size_t)row * Cc))[t] = make_uint2(h0, h1);
    ((uint2*)(lo + (size_t)row * Cc))[t] = make_uint2(l0, l1);
}

// ================= mma.sync split-bf16 GEMM (2 CTAs/SM) =================
// C[M,N] = A[M,K] @ B[N,K]^T via AhiBhi + AhiBlo + AloBhi, fp32 accum.
// EPI: 1 +bias+res fp32 | 2 +bias,ELU->bf16 split | 3 +bias,ELU,BN,+res fp32
// EPI 4: plain -> bf16 hi/lo split (lo stored only for K cols [Cc,2Cc))
#define BK      32
#define SSTRIDE 40                     // bf16 elems per smem row (32 + 8 pad)
#define TILE_B  (128 * SSTRIDE * 2)    // 10240 bytes per tile buffer
#define STAGE_B (4 * TILE_B)           // 40960
#define HG_SMEM (2 * STAGE_B)          // 81920  -> 2 CTAs/SM

template <int EPI>
__global__ __launch_bounds__(256, 2)
void hgemm_k(const __nv_bfloat16* __restrict__ Ahi, const __nv_bfloat16* __restrict__ Alo,
             const __nv_bfloat16* __restrict__ Bhi, const __nv_bfloat16* __restrict__ Blo,
             float* __restrict__ Cf, __nv_bfloat16* __restrict__ Chi, __nv_bfloat16* __restrict__ Clo,
             const float* __restrict__ bias, const float* __restrict__ res,
             const float* __restrict__ bng, const float* __restrict__ bnb,
             const float* __restrict__ bnm, const float* __restrict__ bnv,
             int Ndim, int Kdim)
{
    extern __shared__ char dsm[];
    const int tid = threadIdx.x;
    const int wid = tid >> 5, lid = tid & 31;
    const int m_blk = blockIdx.y * 128, n_blk = blockIdx.x * 128;
    const int wm = wid & 3, wn = wid >> 2;

    const uint32_t sbase = smem_u32(dsm);

    float acc[2][8][4];
    #pragma unroll
    for (int i = 0; i < 2; i++)
        #pragma unroll
        for (int j = 0; j < 8; j++)
            #pragma unroll
            for (int q = 0; q < 4; q++) acc[i][j][q] = 0.f;

    const int a_row = 32 * wm + (lid & 15);
    const int a_col = (lid >> 4) * 8;
    const int b_row = 64 * wn + ((lid & 16) >> 1) + (lid & 7);
    const int b_col = (lid & 8);

    auto load_stage = [&](int c) {
        const int kk = c * BK;
        const uint32_t sb = sbase + (c & 1) * STAGE_B;
        #pragma unroll
        for (int it = 0; it < 2; ++it) {
            int id = tid + it * 256;
            int row = id >> 2, seg = id & 3;
            uint32_t so = (uint32_t)(row * SSTRIDE + seg * 8) * 2;
            size_t ga = (size_t)(m_blk + row) * Kdim + kk + seg * 8;
            size_t gb = (size_t)(n_blk + row) * Kdim + kk + seg * 8;
            CP_ASYNC(sb + so,              Ahi + ga);
            CP_ASYNC(sb + TILE_B + so,     Alo + ga);
            CP_ASYNC(sb + 2 * TILE_B + so, Bhi + gb);
            CP_ASYNC(sb + 3 * TILE_B + so, Blo + gb);
        }
        CP_COMMIT();
    };

    const int nchunk = Kdim / BK;
    load_stage(0);
    for (int c = 0; c < nchunk; ++c) {
        if (c + 1 < nchunk) { load_stage(c + 1); CP_WAIT1(); }
        else                { CP_WAIT0(); }
        __syncthreads();
        const uint32_t sb = sbase + (c & 1) * STAGE_B;
        #pragma unroll
        for (int k16 = 0; k16 < BK / 16; ++k16) {
            uint32_t ah[2][4], al[2][4];
            #pragma unroll
            for (int i = 0; i < 2; ++i) {
                uint32_t ao = sb + (uint32_t)((a_row + 16 * i) * SSTRIDE + a_col + 16 * k16) * 2;
                ldsm_x4(ah[i][0], ah[i][1], ah[i][2], ah[i][3], ao);
                ldsm_x4(al[i][0], al[i][1], al[i][2], al[i][3], ao + TILE_B);
            }
            #pragma unroll
            for (int jg = 0; jg < 2; ++jg) {          // groups of 4 j-frags
                uint32_t bh[4][2], bl[4][2];
                #pragma unroll
                for (int jj = 0; jj < 2; ++jj) {
                    uint32_t bo = sb + 2 * TILE_B
                                + (uint32_t)((32 * jg + 16 * jj + b_row) * SSTRIDE + b_col + 16 * k16) * 2;
                    ldsm_x4(bh[2*jj][0], bh[2*jj][1], bh[2*jj+1][0], bh[2*jj+1][1], bo);
                    ldsm_x4(bl[2*jj][0], bl[2*jj][1], bl[2*jj+1][0], bl[2*jj+1][1], bo + TILE_B);
                }
                #pragma unroll
                for (int i = 0; i < 2; ++i)
                    #pragma unroll
                    for (int j = 0; j < 4; ++j) {
                        mma_bf16(acc[i][4*jg + j], ah[i], bh[j]);
                        mma_bf16(acc[i][4*jg + j], ah[i], bl[j]);
                        mma_bf16(acc[i][4*jg + j], al[i], bh[j]);
                    }
            }
        }
        __syncthreads();
    }

    const bool store_lo = (EPI == 2) || (EPI == 4 && n_blk >= Cc && n_blk < 2 * Cc);
    #pragma unroll
    for (int i = 0; i < 2; ++i) {
        #pragma unroll
        for (int half = 0; half < 2; ++half) {
            const int r = m_blk + 32 * wm + 16 * i + (lid >> 2) + 8 * half;
            #pragma unroll
            for (int j = 0; j < 8; ++j) {
                const int c = n_blk + 64 * wn + 8 * j + 2 * (lid & 3);
                float v0 = acc[i][j][2 * half + 0];
                float v1 = acc[i][j][2 * half + 1];
                if (EPI == 1) {
                    const float2 rv = *(const float2*)(res + (size_t)r * Ndim + c);
                    v0 += __ldg(bias + c)     + rv.x;
                    v1 += __ldg(bias + c + 1) + rv.y;
                } else if (EPI == 2) {
                    v0 += __ldg(bias + c);
                    v1 += __ldg(bias + c + 1);
                    v0 = (v0 > 0.f) ? v0 : expm1f(v0);
                    v1 = (v1 > 0.f) ? v1 : expm1f(v1);
                } else if (EPI == 3) {
                    const float2 rv = *(const float2*)(res + (size_t)r * Ndim + c);
                    v0 += __ldg(bias + c);
                    v1 += __ldg(bias + c + 1);
                    v0 = (v0 > 0.f) ? v0 : expm1f(v0);
                    v1 = (v1 > 0.f) ? v1 : expm1f(v1);
                    v0 = (v0 - __ldg(bnm + c))     * rsqrtf(__ldg(bnv + c) + EPS)     * __ldg(bng + c)     + __ldg(bnb + c)     + rv.x;
                    v1 = (v1 - __ldg(bnm + c + 1)) * rsqrtf(__ldg(bnv + c + 1) + EPS) * __ldg(bng + c + 1) + __ldg(bnb + c + 1) + rv.y;
                }
                if (EPI == 2 || EPI == 4) {
                    uint32_t hp, lp;
                    split2(v0, v1, hp, lp);
                    *(uint32_t*)(Chi + (size_t)r * Ndim + c) = hp;
                    if (store_lo) *(uint32_t*)(Clo + (size_t)r * Ndim + c) = lp;
                } else {
                    *(float2*)(Cf + (size_t)r * Ndim + c) = make_float2(v0, v1);
                }
            }
        }
    }
}

// ================= Tensor-core flash attention =================
// BQ=128, BK=64, 8 warps x 16 q-rows. Q hi only (Qlo term dropped);
// K hi/lo + V double-buffered. S = Qhi*Khi + Qhi*Klo.
#define FQSTR     136
#define FQ_B      (128 * FQSTR * 2)        // 34816
#define FK_B      (64 * FQSTR * 2)         // 17408
#define FSTAGE_B  (3 * FK_B)               // Khi | Klo | V
#define FLASH_SMEM (FQ_B + 2 * FSTAGE_B)   // 139264

__global__ __launch_bounds__(256, 1)
void flash_tc_k(const __nv_bfloat16* __restrict__ qkv_hi,
                const __nv_bfloat16* __restrict__ qkv_lo,
                __nv_bfloat16* __restrict__ out_hi, __nv_bfloat16* __restrict__ out_lo)
{
    extern __shared__ char fsm[];
    const int tid = threadIdx.x, wid = tid >> 5, lid = tid & 31;
    const int bh_i = blockIdx.y, b = bh_i >> 3, h = bh_i & 7;
    const int q0 = blockIdx.x * 128;
    const size_t base = (size_t)b * Nn * C3 + h * Dd;

    const uint32_t sQhi = smem_u32(fsm);
    const uint32_t sKV  = sQhi + FQ_B;

    // ---- Q hi load: 128 rows x 16 segs of 16B ----
    #pragma unroll
    for (int it = 0; it < 8; ++it) {
        int idx = tid + it * 256;
        int row = idx >> 4, seg = idx & 15;
        uint32_t so = (uint32_t)row * (FQSTR * 2) + seg * 16;
        CP_ASYNC(sQhi + so, qkv_hi + base + (size_t)(q0 + row) * C3 + seg * 8);
    }

    auto load_kv = [&](int kt) {
        const uint32_t sb = sKV + (kt & 1) * FSTAGE_B;
        #pragma unroll
        for (int it = 0; it < 4; ++it) {
            int idx = tid + it * 256;
            int row = idx >> 4, seg = idx & 15;
            uint32_t so = (uint32_t)row * (FQSTR * 2) + seg * 16;
            size_t gk = base + (size_t)(kt * 64 + row) * C3 + Cc + seg * 8;
            size_t gv = base + (size_t)(kt * 64 + row) * C3 + 2 * Cc + seg * 8;
            CP_ASYNC(sb + so,            qkv_hi + gk);
            CP_ASYNC(sb + FK_B + so,     qkv_lo + gk);
            CP_ASYNC(sb + 2 * FK_B + so, qkv_hi + gv);
        }
        CP_COMMIT();
    };

    load_kv(0);   // commit bundles Q loads too

    const float SCL = ATT_SCALE * 1.4426950408889634f;
    float m0 = -1e30f, m1 = -1e30f, l0 = 0.f, l1 = 0.f;
    float accO[16][4];
    #pragma unroll
    for (int j = 0; j < 16; ++j)
        #pragma unroll
        for (int q = 0; q < 4; ++q) accO[j][q] = 0.f;

    const uint32_t a_off0 = (uint32_t)((16 * wid + (lid & 15)) * FQSTR + (lid >> 4) * 8) * 2;
    const int b_rl = ((lid & 16) >> 1) + (lid & 7);
    const int b_cl = (lid & 8);
    const int v_rl = (lid & 8) + (lid & 7);
    const int v_cl = ((lid & 16) >> 1);

    const int NT = Nn / 64;
    for (int kt = 0; kt < NT; ++kt) {
        if (kt + 1 < NT) { load_kv(kt + 1); CP_WAIT1(); }
        else             { CP_WAIT0(); }
        __syncthreads();
        const uint32_t sb = sKV + (kt & 1) * FSTAGE_B;

        // ---- S = Qhi (Khi + Klo)^T ----
        float accS[8][4];
        #pragma unroll
        for (int j = 0; j < 8; ++j)
            #pragma unroll
            for (int q = 0; q < 4; ++q) accS[j][q] = 0.f;

        #pragma unroll
        for (int k16 = 0; k16 < 8; ++k16) {
            uint32_t ah[4];
            uint32_t ao = sQhi + a_off0 + (uint32_t)(16 * k16) * 2;
            ldsm_x4(ah[0], ah[1], ah[2], ah[3], ao);
            #pragma unroll
            for (int jj = 0; jj < 4; ++jj) {
                uint32_t bh[2][2], bl[2][2];
                uint32_t bo = sb + (uint32_t)((16 * jj + b_rl) * FQSTR + b_cl + 16 * k16) * 2;
                ldsm_x4(bh[0][0], bh[0][1], bh[1][0], bh[1][1], bo);
                ldsm_x4(bl[0][0], bl[0][1], bl[1][0], bl[1][1], bo + FK_B);
                #pragma unroll
                for (int t = 0; t < 2; ++t) {
                    mma_bf16(accS[2*jj+t], ah, bh[t]);
                    mma_bf16(accS[2*jj+t], ah, bl[t]);
                }
            }
        }

        // ---- online softmax ----
        float mx0 = -1e30f, mx1 = -1e30f;
        #pragma unroll
        for (int j = 0; j < 8; ++j) {
            mx0 = fmaxf(mx0, fmaxf(accS[j][0], accS[j][1]));
            mx1 = fmaxf(mx1, fmaxf(accS[j][2], accS[j][3]));
        }
        mx0 = fmaxf(mx0, __shfl_xor_sync(0xffffffffu, mx0, 1));
        mx0 = fmaxf(mx0, __shfl_xor_sync(0xffffffffu, mx0, 2));
        mx1 = fmaxf(mx1, __shfl_xor_sync(0xffffffffu, mx1, 1));
        mx1 = fmaxf(mx1, __shfl_xor_sync(0xffffffffu, mx1, 2));
        mx0 *= SCL; mx1 *= SCL;
        float mn0 = fmaxf(m0, mx0), mn1 = fmaxf(m1, mx1);
        float al0 = exp2f(m0 - mn0), al1 = exp2f(m1 - mn1);
        m0 = mn0; m1 = mn1;

        float ls0 = 0.f, ls1 = 0.f;
        #pragma unroll
        for (int j = 0; j < 8; ++j) {
            float p0 = exp2f(accS[j][0] * SCL - mn0);
            float p1 = exp2f(accS[j][1] * SCL - mn0);
            float p2 = exp2f(accS[j][2] * SCL - mn1);
            float p3 = exp2f(accS[j][3] * SCL - mn1);
            accS[j][0] = p0; accS[j][1] = p1; accS[j][2] = p2; accS[j][3] = p3;
            ls0 += p0 + p1; ls1 += p2 + p3;
        }
        ls0 += __shfl_xor_sync(0xffffffffu, ls0, 1);
        ls0 += __shfl_xor_sync(0xffffffffu, ls0, 2);
        ls1 += __shfl_xor_sync(0xffffffffu, ls1, 1);
        ls1 += __shfl_xor_sync(0xffffffffu, ls1, 2);
        l0 = l0 * al0 + ls0;
        l1 = l1 * al1 + ls1;

        #pragma unroll
        for (int j = 0; j < 16; ++j) {
            accO[j][0] *= al0; accO[j][1] *= al0;
            accO[j][2] *= al1; accO[j][3] *= al1;
        }

        uint32_t pa[4][4];
        #pragma unroll
        for (int kk = 0; kk < 4; ++kk) {
            pa[kk][0] = cvt2bf(accS[2*kk][0],   accS[2*kk][1]);
            pa[kk][1] = cvt2bf(accS[2*kk][2],   accS[2*kk][3]);
            pa[kk][2] = cvt2bf(accS[2*kk+1][0], accS[2*kk+1][1]);
            pa[kk][3] = cvt2bf(accS[2*kk+1][2], accS[2*kk+1][3]);
        }

        // ---- O += P V ----
        #pragma unroll
        for (int kk = 0; kk < 4; ++kk) {
            #pragma unroll
            for (int jj = 0; jj < 8; ++jj) {
                uint32_t r0, r1, r2, r3;
                uint32_t vo = sb + 2 * FK_B
                            + (uint32_t)((16 * kk + v_rl) * FQSTR + 16 * jj + v_cl) * 2;
                ldsm_x4_t(r0, r1, r2, r3, vo);
                uint32_t vb0[2] = {r0, r1}, vb1[2] = {r2, r3};
                mma_bf16(accO[2*jj],     pa[kk], vb0);
                mma_bf16(accO[2*jj + 1], pa[kk], vb1);
            }
        }
        __syncthreads();
    }

    // ---- epilogue ----
    float inv0 = 1.f / l0, inv1 = 1.f / l1;
    const int row0 = q0 + 16 * wid + (lid >> 2);
    #pragma unroll
    for (int j = 0; j < 16; ++j) {
        const int col = h * Dd + 8 * j + 2 * (lid & 3);
        uint32_t hp, lp;
        split2(accO[j][0] * inv0, accO[j][1] * inv0, hp, lp);
        size_t o0 = ((size_t)b * Nn + row0) * Cc + col;
        *(uint32_t*)(out_hi + o0) = hp;
        *(uint32_t*)(out_lo + o0) = lp;
        split2(accO[j][2] * inv1, accO[j][3] * inv1, hp, lp);
        size_t o1 = ((size_t)b * Nn + row0 + 8) * Cc + col;
        *(uint32_t*)(out_hi + o1) = hp;
        *(uint32_t*)(out_lo + o1) = lp;
    }
}

// ================= host launcher =================
extern "C" void kernel_launch(void* const* d_in, const int* in_sizes, int n_in,
                              void* d_out, int out_size)
{
    const float* x       = (const float*)d_in[0];
    const float* ln1_g   = (const float*)d_in[1];
    const float* ln1_b   = (const float*)d_in[2];
    const float* w_qkv   = (const float*)d_in[3];
    const float* w_proj  = (const float*)d_in[4];
    const float* b_proj  = (const float*)d_in[5];
    const float* ln2_g   = (const float*)d_in[6];
    const float* ln2_b   = (const float*)d_in[7];
    const float* w1      = (const float*)d_in[8];
    const float* b1      = (const float*)d_in[9];
    const float* w2      = (const float*)d_in[10];
    const float* b2      = (const float*)d_in[11];
    const float* bn_g    = (const float*)d_in[12];
    const float* bn_b    = (const float*)d_in[13];
    const float* bn_mean = (const float*)d_in[14];
    const float* bn_var  = (const float*)d_in[15];
    float* out = (float*)d_out;

    float *p_x1;
    __nv_bfloat16 *p_qkv_hi, *p_qkv_lo;
    __nv_bfloat16 *p_h_hi, *p_h_lo, *p_attn_hi, *p_attn_lo, *p_h1_hi, *p_h1_lo;
    __nv_bfloat16 *p_wqkv_hi, *p_wqkv_lo, *p_wproj_hi, *p_wproj_lo;
    __nv_bfloat16 *p_w1_hi, *p_w1_lo, *p_w2_hi, *p_w2_lo;
    cudaGetSymbolAddress((void**)&p_x1,       g_x1);
    cudaGetSymbolAddress((void**)&p_qkv_hi,   g_qkv_hi);
    cudaGetSymbolAddress((void**)&p_qkv_lo,   g_qkv_lo);
    cudaGetSymbolAddress((void**)&p_h_hi,     g_h_hi);
    cudaGetSymbolAddress((void**)&p_h_lo,     g_h_lo);
    cudaGetSymbolAddress((void**)&p_attn_hi,  g_attn_hi);
    cudaGetSymbolAddress((void**)&p_attn_lo,  g_attn_lo);
    cudaGetSymbolAddress((void**)&p_h1_hi,    g_h1_hi);
    cudaGetSymbolAddress((void**)&p_h1_lo,    g_h1_lo);
    cudaGetSymbolAddress((void**)&p_wqkv_hi,  g_wqkv_hi);
    cudaGetSymbolAddress((void**)&p_wqkv_lo,  g_wqkv_lo);
    cudaGetSymbolAddress((void**)&p_wproj_hi, g_wproj_hi);
    cudaGetSymbolAddress((void**)&p_wproj_lo, g_wproj_lo);
    cudaGetSymbolAddress((void**)&p_w1_hi,    g_w1_hi);
    cudaGetSymbolAddress((void**)&p_w1_lo,    g_w1_lo);
    cudaGetSymbolAddress((void**)&p_w2_hi,    g_w2_hi);
    cudaGetSymbolAddress((void**)&p_w2_lo,    g_w2_lo);

    cudaFuncSetAttribute(hgemm_k<1>, cudaFuncAttributeMaxDynamicSharedMemorySize, HG_SMEM);
    cudaFuncSetAttribute(hgemm_k<2>, cudaFuncAttributeMaxDynamicSharedMemorySize, HG_SMEM);
    cudaFuncSetAttribute(hgemm_k<3>, cudaFuncAttributeMaxDynamicSharedMemorySize, HG_SMEM);
    cudaFuncSetAttribute(hgemm_k<4>, cudaFuncAttributeMaxDynamicSharedMemorySize, HG_SMEM);
    cudaFuncSetAttribute(flash_tc_k, cudaFuncAttributeMaxDynamicSharedMemorySize, FLASH_SMEM);

    // fused weight splits (one launch)
    cvt_split_all_k<<<6144, 256>>>(w_qkv, w_proj, w1, w2,
                                   p_wqkv_hi, p_wqkv_lo, p_wproj_hi, p_wproj_lo,
                                   p_w1_hi, p_w1_lo, p_w2_hi, p_w2_lo);

    // LN1 -> hi/lo
    layernorm_bf_k<<<Mm, 256>>>(x, ln1_g, ln1_b, p_h_hi, p_h_lo);

    // QKV GEMM -> bf16 hi (lo only for K cols) (EPI 4)
    hgemm_k<4><<<dim3(C3 / 128, Mm / 128), 256, HG_SMEM>>>(
        p_h_hi, p_h_lo, p_wqkv_hi, p_wqkv_lo,
        nullptr, p_qkv_hi, p_qkv_lo,
        nullptr, nullptr, nullptr, nullptr, nullptr, nullptr,
        C3, Cc);

    // Tensor-core flash attention -> attn hi/lo
    flash_tc_k<<<dim3(Nn / 128, Bz * Hh), 256, FLASH_SMEM>>>(
        p_qkv_hi, p_qkv_lo, p_attn_hi, p_attn_lo);

    // proj GEMM + bias + residual -> x1 fp32 (EPI 1)
    hgemm_k<1><<<dim3(Cc / 128, Mm / 128), 256, HG_SMEM>>>(
        p_attn_hi, p_attn_lo, p_wproj_hi, p_wproj_lo,
        p_x1, nullptr, nullptr,
        b_proj, x, nullptr, nullptr, nullptr, nullptr,
        Cc, Cc);

    // LN2 -> hi/lo
    layernorm_bf_k<<<Mm, 256>>>(p_x1, ln2_g, ln2_b, p_h_hi, p_h_lo);

    // MLP1: ELU(h @ w1^T + b1) -> h1 hi/lo (EPI 2)
    hgemm_k<2><<<dim3(Cc / 128, Mm / 128), 256, HG_SMEM>>>(
        p_h_hi, p_h_lo, p_w1_hi, p_w1_lo,
        nullptr, p_h1_hi, p_h1_lo,
        b1, nullptr, nullptr, nullptr, nullptr, nullptr,
        Cc, Cc);

    // MLP2: out = x1 + BN(ELU(h1 @ w2^T + b2)) (EPI 3)
    hgemm_k<3><<<dim3(Cc / 128, Mm / 128), 256, HG_SMEM>>>(
        p_h1_hi, p_h1_lo, p_w2_hi, p_w2_lo,
        out, nullptr, nullptr,
        b2, p_x1, bn_g, bn_b, bn_mean, bn_var,
        Cc, Cc);
}

// round 13
// speedup vs baseline: 4.1008x; 1.0972x over previous
#include <cuda_runtime.h>
#include <cuda_bf16.h>
#include <math.h>
#include <stdint.h>

// Problem constants
#define Bz   4
#define Nn   2048
#define Cc   1024
#define Hh   8
#define Dd   128
#define Mm   (Bz * Nn)          // 8192 tokens
#define C3   (3 * Cc)           // 3072
#define EPS  1e-5f
#define ATT_SCALE 0.08838834764831845f  // 128^-0.5

// ================= PTX helpers =================
__device__ __forceinline__ uint32_t smem_u32(const void* p) {
    uint32_t a;
    asm("{ .reg .u64 t; cvta.to.shared.u64 t, %1; cvt.u32.u64 %0, t; }" : "=r"(a) : "l"(p));
    return a;
}
#define CP_ASYNC(dst, src) \
    asm volatile("cp.async.cg.shared.global [%0], [%1], 16;" :: "r"(dst), "l"(src))
#define CP_COMMIT() asm volatile("cp.async.commit_group;" ::: "memory")
#define CP_WAIT1()  asm volatile("cp.async.wait_group 1;" ::: "memory")
#define CP_WAIT0()  asm volatile("cp.async.wait_group 0;" ::: "memory")

__device__ __forceinline__ void ldsm_x4(uint32_t& r0, uint32_t& r1, uint32_t& r2, uint32_t& r3,
                                        uint32_t addr) {
    asm volatile("ldmatrix.sync.aligned.m8n8.x4.shared.b16 {%0,%1,%2,%3}, [%4];"
                 : "=r"(r0), "=r"(r1), "=r"(r2), "=r"(r3) : "r"(addr));
}
__device__ __forceinline__ void ldsm_x4_t(uint32_t& r0, uint32_t& r1, uint32_t& r2, uint32_t& r3,
                                          uint32_t addr) {
    asm volatile("ldmatrix.sync.aligned.m8n8.x4.trans.shared.b16 {%0,%1,%2,%3}, [%4];"
                 : "=r"(r0), "=r"(r1), "=r"(r2), "=r"(r3) : "r"(addr));
}
__device__ __forceinline__ void mma_bf16(float* d, const uint32_t* a, const uint32_t* b) {
    asm volatile(
        "mma.sync.aligned.m16n8k16.row.col.f32.bf16.bf16.f32 "
        "{%0,%1,%2,%3}, {%4,%5,%6,%7}, {%8,%9}, {%0,%1,%2,%3};"
        : "+f"(d[0]), "+f"(d[1]), "+f"(d[2]), "+f"(d[3])
        : "r"(a[0]), "r"(a[1]), "r"(a[2]), "r"(a[3]), "r"(b[0]), "r"(b[1]));
}

__device__ __forceinline__ void split2(float a, float b, uint32_t& hp, uint32_t& lp) {
    __nv_bfloat16 ha = __float2bfloat16(a), hb = __float2bfloat16(b);
    float ra = a - __bfloat162float(ha), rb = b - __bfloat162float(hb);
    __nv_bfloat16 la = __float2bfloat16(ra), lb = __float2bfloat16(rb);
    hp = (uint32_t)__bfloat16_as_ushort(ha) | ((uint32_t)__bfloat16_as_ushort(hb) << 16);
    lp = (uint32_t)__bfloat16_as_ushort(la) | ((uint32_t)__bfloat16_as_ushort(lb) << 16);
}
__device__ __forceinline__ uint32_t cvt2bf(float a, float b) {
    __nv_bfloat162 t = __floats2bfloat162_rn(a, b);
    return *(uint32_t*)&t;
}

// ================= scratch (device globals) =================
__device__ float g_x1 [Mm * Cc];
__device__ __nv_bfloat16 g_qkv_hi[Mm * C3];
__device__ __nv_bfloat16 g_h_hi   [Mm * Cc], g_h_lo   [Mm * Cc];
__device__ __nv_bfloat16 g_attn_hi[Mm * Cc], g_attn_lo[Mm * Cc];
__device__ __nv_bfloat16 g_h1_hi  [Mm * Cc], g_h1_lo  [Mm * Cc];
__device__ __nv_bfloat16 g_wqkv_hi [C3 * Cc], g_wqkv_lo [C3 * Cc];
__device__ __nv_bfloat16 g_wproj_hi[Cc * Cc], g_wproj_lo[Cc * Cc];
__device__ __nv_bfloat16 g_w1_hi   [Cc * Cc], g_w1_lo   [Cc * Cc];
__device__ __nv_bfloat16 g_w2_hi   [Cc * Cc], g_w2_lo   [Cc * Cc];

// ================= fused fp32 -> bf16 hi/lo converter (all 4 weights) ========
__global__ void cvt_split_all_k(const float* __restrict__ wqkv, const float* __restrict__ wproj,
                                const float* __restrict__ w1, const float* __restrict__ w2,
                                __nv_bfloat16* __restrict__ qkv_hi, __nv_bfloat16* __restrict__ qkv_lo,
                                __nv_bfloat16* __restrict__ proj_hi, __nv_bfloat16* __restrict__ proj_lo,
                                __nv_bfloat16* __restrict__ w1_hi, __nv_bfloat16* __restrict__ w1_lo,
                                __nv_bfloat16* __restrict__ w2_hi, __nv_bfloat16* __restrict__ w2_lo)
{
    int blk = blockIdx.x;
    const float* src;
    __nv_bfloat16 *hi, *lo;
    int local;
    if (blk < 3072)      { src = wqkv;  hi = qkv_hi;  lo = qkv_lo;  local = blk; }
    else if (blk < 4096) { src = wproj; hi = proj_hi; lo = proj_lo; local = blk - 3072; }
    else if (blk < 5120) { src = w1;    hi = w1_hi;   lo = w1_lo;   local = blk - 4096; }
    else                 { src = w2;    hi = w2_hi;   lo = w2_lo;   local = blk - 5120; }
    int i = local * 256 + threadIdx.x;
    float4 v = ((const float4*)src)[i];
    uint32_t h0, l0, h1, l1;
    split2(v.x, v.y, h0, l0);
    split2(v.z, v.w, h1, l1);
    ((uint2*)hi)[i] = make_uint2(h0, h1);
    ((uint2*)lo)[i] = make_uint2(l0, l1);
}

// ================= LayerNorm -> bf16 hi/lo =================
__global__ void layernorm_bf_k(const float* __restrict__ in, const float* __restrict__ g,
                               const float* __restrict__ b,
                               __nv_bfloat16* __restrict__ hi, __nv_bfloat16* __restrict__ lo)
{
    int row = blockIdx.x;
    int t = threadIdx.x;
    const float4* inr = (const float4*)(in + (size_t)row * Cc);
    float4 v = inr[t];
    float s  = v.x + v.y + v.z + v.w;
    float ss = v.x*v.x + v.y*v.y + v.z*v.z + v.w*v.w;
    #pragma unroll
    for (int o = 16; o; o >>= 1) {
        s  += __shfl_xor_sync(0xffffffffu, s,  o);
        ss += __shfl_xor_sync(0xffffffffu, ss, o);
    }
    __shared__ float sm1[8], sm2[8];
    if ((t & 31) == 0) { sm1[t >> 5] = s; sm2[t >> 5] = ss; }
    __syncthreads();
    if (t < 32) {
        s  = (t < 8) ? sm1[t] : 0.f;
        ss = (t < 8) ? sm2[t] : 0.f;
        #pragma unroll
        for (int o = 4; o; o >>= 1) {
            s  += __shfl_xor_sync(0xffffffffu, s,  o);
            ss += __shfl_xor_sync(0xffffffffu, ss, o);
        }
        if (t == 0) { sm1[0] = s; sm2[0] = ss; }
    }
    __syncthreads();
    float mu  = sm1[0] * (1.f / Cc);
    float var = sm2[0] * (1.f / Cc) - mu * mu;
    float inv = rsqrtf(var + EPS);
    float4 gv = ((const float4*)g)[t];
    float4 bv = ((const float4*)b)[t];
    float o0 = (v.x - mu) * inv * gv.x + bv.x;
    float o1 = (v.y - mu) * inv * gv.y + bv.y;
    float o2 = (v.z - mu) * inv * gv.z + bv.z;
    float o3 = (v.w - mu) * inv * gv.w + bv.w;
    uint32_t h0, l0, h1, l1;
    split2(o0, o1, h0, l0);
    split2(o2, o3, h1, l1);
    ((uint2*)(hi + (size_t)row * Cc))[t] = make_uint2(h0, h1);
    ((uint2*)(lo + (size_t)row * Cc))[t] = make_uint2(l0, l1);
}

// ================= mma.sync split-bf16 GEMM (2 CTAs/SM) =================
// C[M,N] = A[M,K] @ B[N,K]^T via AhiBhi + AhiBlo + AloBhi, fp32 accum.
// EPI: 1 +bias+res fp32 | 2 +bias,ELU->bf16 split | 3 +bias,ELU,BN,+res fp32
// EPI 4: plain -> bf16 hi only
#define BK      32
#define SSTRIDE 40
#define TILE_B  (128 * SSTRIDE * 2)    // 10240
#define STAGE_B (4 * TILE_B)           // 40960
#define HG_SMEM (2 * STAGE_B)          // 81920 -> 2 CTAs/SM

template <int EPI>
__global__ __launch_bounds__(256, 2)
void hgemm_k(const __nv_bfloat16* __restrict__ Ahi, const __nv_bfloat16* __restrict__ Alo,
             const __nv_bfloat16* __restrict__ Bhi, const __nv_bfloat16* __restrict__ Blo,
             float* __restrict__ Cf, __nv_bfloat16* __restrict__ Chi, __nv_bfloat16* __restrict__ Clo,
             const float* __restrict__ bias, const float* __restrict__ res,
             const float* __restrict__ bng, const float* __restrict__ bnb,
             const float* __restrict__ bnm, const float* __restrict__ bnv,
             int Ndim, int Kdim)
{
    extern __shared__ char dsm[];
    const int tid = threadIdx.x;
    const int wid = tid >> 5, lid = tid & 31;
    const int m_blk = blockIdx.y * 128, n_blk = blockIdx.x * 128;
    const int wm = wid & 3, wn = wid >> 2;

    const uint32_t sbase = smem_u32(dsm);

    float acc[2][8][4];
    #pragma unroll
    for (int i = 0; i < 2; i++)
        #pragma unroll
        for (int j = 0; j < 8; j++)
            #pragma unroll
            for (int q = 0; q < 4; q++) acc[i][j][q] = 0.f;

    const int a_row = 32 * wm + (lid & 15);
    const int a_col = (lid >> 4) * 8;
    const int b_row = 64 * wn + ((lid & 16) >> 1) + (lid & 7);
    const int b_col = (lid & 8);

    auto load_stage = [&](int c) {
        const int kk = c * BK;
        const uint32_t sb = sbase + (c & 1) * STAGE_B;
        #pragma unroll
        for (int it = 0; it < 2; ++it) {
            int id = tid + it * 256;
            int row = id >> 2, seg = id & 3;
            uint32_t so = (uint32_t)(row * SSTRIDE + seg * 8) * 2;
            size_t ga = (size_t)(m_blk + row) * Kdim + kk + seg * 8;
            size_t gb = (size_t)(n_blk + row) * Kdim + kk + seg * 8;
            CP_ASYNC(sb + so,              Ahi + ga);
            CP_ASYNC(sb + TILE_B + so,     Alo + ga);
            CP_ASYNC(sb + 2 * TILE_B + so, Bhi + gb);
            CP_ASYNC(sb + 3 * TILE_B + so, Blo + gb);
        }
        CP_COMMIT();
    };

    const int nchunk = Kdim / BK;
    load_stage(0);
    for (int c = 0; c < nchunk; ++c) {
        if (c + 1 < nchunk) { load_stage(c + 1); CP_WAIT1(); }
        else                { CP_WAIT0(); }
        __syncthreads();
        const uint32_t sb = sbase + (c & 1) * STAGE_B;
        #pragma unroll
        for (int k16 = 0; k16 < BK / 16; ++k16) {
            uint32_t ah[2][4], al[2][4];
            #pragma unroll
            for (int i = 0; i < 2; ++i) {
                uint32_t ao = sb + (uint32_t)((a_row + 16 * i) * SSTRIDE + a_col + 16 * k16) * 2;
                ldsm_x4(ah[i][0], ah[i][1], ah[i][2], ah[i][3], ao);
                ldsm_x4(al[i][0], al[i][1], al[i][2], al[i][3], ao + TILE_B);
            }
            #pragma unroll
            for (int jg = 0; jg < 2; ++jg) {
                uint32_t bh[4][2], bl[4][2];
                #pragma unroll
                for (int jj = 0; jj < 2; ++jj) {
                    uint32_t bo = sb + 2 * TILE_B
                                + (uint32_t)((32 * jg + 16 * jj + b_row) * SSTRIDE + b_col + 16 * k16) * 2;
                    ldsm_x4(bh[2*jj][0], bh[2*jj][1], bh[2*jj+1][0], bh[2*jj+1][1], bo);
                    ldsm_x4(bl[2*jj][0], bl[2*jj][1], bl[2*jj+1][0], bl[2*jj+1][1], bo + TILE_B);
                }
                #pragma unroll
                for (int i = 0; i < 2; ++i)
                    #pragma unroll
                    for (int j = 0; j < 4; ++j) {
                        mma_bf16(acc[i][4*jg + j], ah[i], bh[j]);
                        mma_bf16(acc[i][4*jg + j], ah[i], bl[j]);
                        mma_bf16(acc[i][4*jg + j], al[i], bh[j]);
                    }
            }
        }
        __syncthreads();
    }

    #pragma unroll
    for (int i = 0; i < 2; ++i) {
        #pragma unroll
        for (int half = 0; half < 2; ++half) {
            const int r = m_blk + 32 * wm + 16 * i + (lid >> 2) + 8 * half;
            #pragma unroll
            for (int j = 0; j < 8; ++j) {
                const int c = n_blk + 64 * wn + 8 * j + 2 * (lid & 3);
                float v0 = acc[i][j][2 * half + 0];
                float v1 = acc[i][j][2 * half + 1];
                if (EPI == 1) {
                    const float2 rv = *(const float2*)(res + (size_t)r * Ndim + c);
                    v0 += __ldg(bias + c)     + rv.x;
                    v1 += __ldg(bias + c + 1) + rv.y;
                } else if (EPI == 2) {
                    v0 += __ldg(bias + c);
                    v1 += __ldg(bias + c + 1);
                    v0 = (v0 > 0.f) ? v0 : expm1f(v0);
                    v1 = (v1 > 0.f) ? v1 : expm1f(v1);
                } else if (EPI == 3) {
                    const float2 rv = *(const float2*)(res + (size_t)r * Ndim + c);
                    v0 += __ldg(bias + c);
                    v1 += __ldg(bias + c + 1);
                    v0 = (v0 > 0.f) ? v0 : expm1f(v0);
                    v1 = (v1 > 0.f) ? v1 : expm1f(v1);
                    v0 = (v0 - __ldg(bnm + c))     * rsqrtf(__ldg(bnv + c) + EPS)     * __ldg(bng + c)     + __ldg(bnb + c)     + rv.x;
                    v1 = (v1 - __ldg(bnm + c + 1)) * rsqrtf(__ldg(bnv + c + 1) + EPS) * __ldg(bng + c + 1) + __ldg(bnb + c + 1) + rv.y;
                }
                if (EPI == 2) {
                    uint32_t hp, lp;
                    split2(v0, v1, hp, lp);
                    *(uint32_t*)(Chi + (size_t)r * Ndim + c) = hp;
                    *(uint32_t*)(Clo + (size_t)r * Ndim + c) = lp;
                } else if (EPI == 4) {
                    *(uint32_t*)(Chi + (size_t)r * Ndim + c) = cvt2bf(v0, v1);
                } else {
                    *(float2*)(Cf + (size_t)r * Ndim + c) = make_float2(v0, v1);
                }
            }
        }
    }
}

// ================= Tensor-core flash attention (pure bf16 QK, 2 CTAs/SM) ====
// BQ=128, BK=64, 8 warps x 16 q-rows. Q resident; K + V double-buffered.
#define FQSTR     136
#define FQ_B      (128 * FQSTR * 2)        // 34816
#define FK_B      (64 * FQSTR * 2)         // 17408
#define FSTAGE_B  (2 * FK_B)               // K | V  = 34816
#define FLASH_SMEM (FQ_B + 2 * FSTAGE_B)   // 104448 -> 2 CTAs/SM

__global__ __launch_bounds__(256, 2)
void flash_tc_k(const __nv_bfloat16* __restrict__ qkv_hi,
                __nv_bfloat16* __restrict__ out_hi, __nv_bfloat16* __restrict__ out_lo)
{
    extern __shared__ char fsm[];
    const int tid = threadIdx.x, wid = tid >> 5, lid = tid & 31;
    const int bh_i = blockIdx.y, b = bh_i >> 3, h = bh_i & 7;
    const int q0 = blockIdx.x * 128;
    const size_t base = (size_t)b * Nn * C3 + h * Dd;

    const uint32_t sQ  = smem_u32(fsm);
    const uint32_t sKV = sQ + FQ_B;

    // ---- Q load: 128 rows x 16 segs of 16B ----
    #pragma unroll
    for (int it = 0; it < 8; ++it) {
        int idx = tid + it * 256;
        int row = idx >> 4, seg = idx & 15;
        uint32_t so = (uint32_t)row * (FQSTR * 2) + seg * 16;
        CP_ASYNC(sQ + so, qkv_hi + base + (size_t)(q0 + row) * C3 + seg * 8);
    }

    auto load_kv = [&](int kt) {
        const uint32_t sb = sKV + (kt & 1) * FSTAGE_B;
        #pragma unroll
        for (int it = 0; it < 4; ++it) {
            int idx = tid + it * 256;
            int row = idx >> 4, seg = idx & 15;
            uint32_t so = (uint32_t)row * (FQSTR * 2) + seg * 16;
            size_t gk = base + (size_t)(kt * 64 + row) * C3 + Cc + seg * 8;
            size_t gv = base + (size_t)(kt * 64 + row) * C3 + 2 * Cc + seg * 8;
            CP_ASYNC(sb + so,        qkv_hi + gk);
            CP_ASYNC(sb + FK_B + so, qkv_hi + gv);
        }
        CP_COMMIT();
    };

    load_kv(0);   // commit bundles Q loads too

    const float SCL = ATT_SCALE * 1.4426950408889634f;
    float m0 = -1e30f, m1 = -1e30f, l0 = 0.f, l1 = 0.f;
    float accO[16][4];
    #pragma unroll
    for (int j = 0; j < 16; ++j)
        #pragma unroll
        for (int q = 0; q < 4; ++q) accO[j][q] = 0.f;

    const uint32_t a_off0 = (uint32_t)((16 * wid + (lid & 15)) * FQSTR + (lid >> 4) * 8) * 2;
    const int b_rl = ((lid & 16) >> 1) + (lid & 7);
    const int b_cl = (lid & 8);
    const int v_rl = (lid & 8) + (lid & 7);
    const int v_cl = ((lid & 16) >> 1);

    const int NT = Nn / 64;
    for (int kt = 0; kt < NT; ++kt) {
        if (kt + 1 < NT) { load_kv(kt + 1); CP_WAIT1(); }
        else             { CP_WAIT0(); }
        __syncthreads();
        const uint32_t sb = sKV + (kt & 1) * FSTAGE_B;

        // ---- S = Q K^T (bf16) ----
        float accS[8][4];
        #pragma unroll
        for (int j = 0; j < 8; ++j)
            #pragma unroll
            for (int q = 0; q < 4; ++q) accS[j][q] = 0.f;

        #pragma unroll
        for (int k16 = 0; k16 < 8; ++k16) {
            uint32_t ah[4];
            uint32_t ao = sQ + a_off0 + (uint32_t)(16 * k16) * 2;
            ldsm_x4(ah[0], ah[1], ah[2], ah[3], ao);
            #pragma unroll
            for (int jj = 0; jj < 4; ++jj) {
                uint32_t bh[2][2];
                uint32_t bo = sb + (uint32_t)((16 * jj + b_rl) * FQSTR + b_cl + 16 * k16) * 2;
                ldsm_x4(bh[0][0], bh[0][1], bh[1][0], bh[1][1], bo);
                mma_bf16(accS[2*jj],     ah, bh[0]);
                mma_bf16(accS[2*jj + 1], ah, bh[1]);
            }
        }

        // ---- online softmax ----
        float mx0 = -1e30f, mx1 = -1e30f;
        #pragma unroll
        for (int j = 0; j < 8; ++j) {
            mx0 = fmaxf(mx0, fmaxf(accS[j][0], accS[j][1]));
            mx1 = fmaxf(mx1, fmaxf(accS[j][2], accS[j][3]));
        }
        mx0 = fmaxf(mx0, __shfl_xor_sync(0xffffffffu, mx0, 1));
        mx0 = fmaxf(mx0, __shfl_xor_sync(0xffffffffu, mx0, 2));
        mx1 = fmaxf(mx1, __shfl_xor_sync(0xffffffffu, mx1, 1));
        mx1 = fmaxf(mx1, __shfl_xor_sync(0xffffffffu, mx1, 2));
        mx0 *= SCL; mx1 *= SCL;
        float mn0 = fmaxf(m0, mx0), mn1 = fmaxf(m1, mx1);
        float al0 = exp2f(m0 - mn0), al1 = exp2f(m1 - mn1);
        m0 = mn0; m1 = mn1;

        float ls0 = 0.f, ls1 = 0.f;
        #pragma unroll
        for (int j = 0; j < 8; ++j) {
            float p0 = exp2f(accS[j][0] * SCL - mn0);
            float p1 = exp2f(accS[j][1] * SCL - mn0);
            float p2 = exp2f(accS[j][2] * SCL - mn1);
            float p3 = exp2f(accS[j][3] * SCL - mn1);
            accS[j][0] = p0; accS[j][1] = p1; accS[j][2] = p2; accS[j][3] = p3;
            ls0 += p0 + p1; ls1 += p2 + p3;
        }
        ls0 += __shfl_xor_sync(0xffffffffu, ls0, 1);
        ls0 += __shfl_xor_sync(0xffffffffu, ls0, 2);
        ls1 += __shfl_xor_sync(0xffffffffu, ls1, 1);
        ls1 += __shfl_xor_sync(0xffffffffu, ls1, 2);
        l0 = l0 * al0 + ls0;
        l1 = l1 * al1 + ls1;

        #pragma unroll
        for (int j = 0; j < 16; ++j) {
            accO[j][0] *= al0; accO[j][1] *= al0;
            accO[j][2] *= al1; accO[j][3] *= al1;
        }

        uint32_t pa[4][4];
        #pragma unroll
        for (int kk = 0; kk < 4; ++kk) {
            pa[kk][0] = cvt2bf(accS[2*kk][0],   accS[2*kk][1]);
            pa[kk][1] = cvt2bf(accS[2*kk][2],   accS[2*kk][3]);
            pa[kk][2] = cvt2bf(accS[2*kk+1][0], accS[2*kk+1][1]);
            pa[kk][3] = cvt2bf(accS[2*kk+1][2], accS[2*kk+1][3]);
        }

        // ---- O += P V ----
        #pragma unroll
        for (int kk = 0; kk < 4; ++kk) {
            #pragma unroll
            for (int jj = 0; jj < 8; ++jj) {
                uint32_t r0, r1, r2, r3;
                uint32_t vo = sb + FK_B
                            + (uint32_t)((16 * kk + v_rl) * FQSTR + 16 * jj + v_cl) * 2;
                ldsm_x4_t(r0, r1, r2, r3, vo);
                uint32_t vb0[2] = {r0, r1}, vb1[2] = {r2, r3};
                mma_bf16(accO[2*jj],     pa[kk], vb0);
                mma_bf16(accO[2*jj + 1], pa[kk], vb1);
            }
        }
        __syncthreads();
    }

    // ---- epilogue ----
    float inv0 = 1.f / l0, inv1 = 1.f / l1;
    const int row0 = q0 + 16 * wid + (lid >> 2);
    #pragma unroll
    for (int j = 0; j < 16; ++j) {
        const int col = h * Dd + 8 * j + 2 * (lid & 3);
        uint32_t hp, lp;
        split2(accO[j][0] * inv0, accO[j][1] * inv0, hp, lp);
        size_t o0 = ((size_t)b * Nn + row0) * Cc + col;
        *(uint32_t*)(out_hi + o0) = hp;
        *(uint32_t*)(out_lo + o0) = lp;
        split2(accO[j][2] * inv1, accO[j][3] * inv1, hp, lp);
        size_t o1 = ((size_t)b * Nn + row0 + 8) * Cc + col;
        *(uint32_t*)(out_hi + o1) = hp;
        *(uint32_t*)(out_lo + o1) = lp;
    }
}

// ================= host launcher =================
extern "C" void kernel_launch(void* const* d_in, const int* in_sizes, int n_in,
                              void* d_out, int out_size)
{
    const float* x       = (const float*)d_in[0];
    const float* ln1_g   = (const float*)d_in[1];
    const float* ln1_b   = (const float*)d_in[2];
    const float* w_qkv   = (const float*)d_in[3];
    const float* w_proj  = (const float*)d_in[4];
    const float* b_proj  = (const float*)d_in[5];
    const float* ln2_g   = (const float*)d_in[6];
    const float* ln2_b   = (const float*)d_in[7];
    const float* w1      = (const float*)d_in[8];
    const float* b1      = (const float*)d_in[9];
    const float* w2      = (const float*)d_in[10];
    const float* b2      = (const float*)d_in[11];
    const float* bn_g    = (const float*)d_in[12];
    const float* bn_b    = (const float*)d_in[13];
    const float* bn_mean = (const float*)d_in[14];
    const float* bn_var  = (const float*)d_in[15];
    float* out = (float*)d_out;

    float *p_x1;
    __nv_bfloat16 *p_qkv_hi;
    __nv_bfloat16 *p_h_hi, *p_h_lo, *p_attn_hi, *p_attn_lo, *p_h1_hi, *p_h1_lo;
    __nv_bfloat16 *p_wqkv_hi, *p_wqkv_lo, *p_wproj_hi, *p_wproj_lo;
    __nv_bfloat16 *p_w1_hi, *p_w1_lo, *p_w2_hi, *p_w2_lo;
    cudaGetSymbolAddress((void**)&p_x1,       g_x1);
    cudaGetSymbolAddress((void**)&p_qkv_hi,   g_qkv_hi);
    cudaGetSymbolAddress((void**)&p_h_hi,     g_h_hi);
    cudaGetSymbolAddress((void**)&p_h_lo,     g_h_lo);
    cudaGetSymbolAddress((void**)&p_attn_hi,  g_attn_hi);
    cudaGetSymbolAddress((void**)&p_attn_lo,  g_attn_lo);
    cudaGetSymbolAddress((void**)&p_h1_hi,    g_h1_hi);
    cudaGetSymbolAddress((void**)&p_h1_lo,    g_h1_lo);
    cudaGetSymbolAddress((void**)&p_wqkv_hi,  g_wqkv_hi);
    cudaGetSymbolAddress((void**)&p_wqkv_lo,  g_wqkv_lo);
    cudaGetSymbolAddress((void**)&p_wproj_hi, g_wproj_hi);
    cudaGetSymbolAddress((void**)&p_wproj_lo, g_wproj_lo);
    cudaGetSymbolAddress((void**)&p_w1_hi,    g_w1_hi);
    cudaGetSymbolAddress((void**)&p_w1_lo,    g_w1_lo);
    cudaGetSymbolAddress((void**)&p_w2_hi,    g_w2_hi);
    cudaGetSymbolAddress((void**)&p_w2_lo,    g_w2_lo);

    cudaFuncSetAttribute(hgemm_k<1>, cudaFuncAttributeMaxDynamicSharedMemorySize, HG_SMEM);
    cudaFuncSetAttribute(hgemm_k<2>, cudaFuncAttributeMaxDynamicSharedMemorySize, HG_SMEM);
    cudaFuncSetAttribute(hgemm_k<3>, cudaFuncAttributeMaxDynamicSharedMemorySize, HG_SMEM);
    cudaFuncSetAttribute(hgemm_k<4>, cudaFuncAttributeMaxDynamicSharedMemorySize, HG_SMEM);
    cudaFuncSetAttribute(flash_tc_k, cudaFuncAttributeMaxDynamicSharedMemorySize, FLASH_SMEM);

    // fused weight splits (one launch)
    cvt_split_all_k<<<6144, 256>>>(w_qkv, w_proj, w1, w2,
                                   p_wqkv_hi, p_wqkv_lo, p_wproj_hi, p_wproj_lo,
                                   p_w1_hi, p_w1_lo, p_w2_hi, p_w2_lo);

    // LN1 -> hi/lo
    layernorm_bf_k<<<Mm, 256>>>(x, ln1_g, ln1_b, p_h_hi, p_h_lo);

    // QKV GEMM -> bf16 hi only (EPI 4)
    hgemm_k<4><<<dim3(C3 / 128, Mm / 128), 256, HG_SMEM>>>(
        p_h_hi, p_h_lo, p_wqkv_hi, p_wqkv_lo,
        nullptr, p_qkv_hi, nullptr,
        nullptr, nullptr, nullptr, nullptr, nullptr, nullptr,
        C3, Cc);

    // Tensor-core flash attention -> attn hi/lo
    flash_tc_k<<<dim3(Nn / 128, Bz * Hh), 256, FLASH_SMEM>>>(
        p_qkv_hi, p_attn_hi, p_attn_lo);

    // proj GEMM + bias + residual -> x1 fp32 (EPI 1)
    hgemm_k<1><<<dim3(Cc / 128, Mm / 128), 256, HG_SMEM>>>(
        p_attn_hi, p_attn_lo, p_wproj_hi, p_wproj_lo,
        p_x1, nullptr, nullptr,
        b_proj, x, nullptr, nullptr, nullptr, nullptr,
        Cc, Cc);

    // LN2 -> hi/lo
    layernorm_bf_k<<<Mm, 256>>>(p_x1, ln2_g, ln2_b, p_h_hi, p_h_lo);

    // MLP1: ELU(h @ w1^T + b1) -> h1 hi/lo (EPI 2)
    hgemm_k<2><<<dim3(Cc / 128, Mm / 128), 256, HG_SMEM>>>(
        p_h_hi, p_h_lo, p_w1_hi, p_w1_lo,
        nullptr, p_h1_hi, p_h1_lo,
        b1, nullptr, nullptr, nullptr, nullptr, nullptr,
        Cc, Cc);

    // MLP2: out = x1 + BN(ELU(h1 @ w2^T + b2)) (EPI 3)
    hgemm_k<3><<<dim3(Cc / 128, Mm / 128), 256, HG_SMEM>>>(
        p_h1_hi, p_h1_lo, p_w2_hi, p_w2_lo,
        out, nullptr, nullptr,
        b2, p_x1, bn_g, bn_b, bn_mean, bn_var,
        Cc, Cc);
}